// round 6
// baseline (speedup 1.0000x reference)
#include <cuda_runtime.h>
#include <cstddef>

typedef unsigned long long ull;
typedef unsigned int uint;

// ---------------- problem constants (shapes fixed by the dataset) -----------
#define MAXN 100000
#define MAXE 1600000
#define MAXET (MAXE + MAXN)
#define FN   128     // node feature dim (layer1 input)
#define FE   32      // edge feature dim
#define HID  64

// ---------------- device scratch (static: no allocation allowed) ------------
__device__ float g_loop[MAXN * FE];        // self-loop edge attr (mean of incoming)
__device__ float g_xl  [MAXN * HID];       // source-side transform
__device__ float g_xr  [MAXN * HID];       // target-side transform
__device__ float g_exc [MAXET];            // exp(logit), CSR slot order
__device__ float g_out [MAXN * HID];       // layer output
__device__ int   g_deg [MAXN];
__device__ int   g_rowptr[MAXN + 1];
__device__ int   g_cur [MAXN];
__device__ int   g_bsum[128];
__device__ int2  g_csr_se [MAXET];         // (src, eid) packed, grouped by dst
__device__ int   g_pos [MAXET];            // eid -> csr slot

// ---------------- small helpers ---------------------------------------------
__device__ __forceinline__ uint to_tf32(float f) {
    uint r; asm("cvt.rna.tf32.f32 %0, %1;" : "=r"(r) : "f"(f)); return r;
}
__device__ __forceinline__ void tf32_split(float v, uint& hb, uint& lb) {
    asm("cvt.rna.tf32.f32 %0, %1;" : "=r"(hb) : "f"(v));
    float hf = __uint_as_float(hb);
    asm("cvt.rna.tf32.f32 %0, %1;" : "=r"(lb) : "f"(v - hf));
}
__device__ __forceinline__ void mma_tf32(float acc[4], const uint a[4], uint b0, uint b1) {
    asm volatile(
        "mma.sync.aligned.m16n8k8.row.col.f32.tf32.tf32.f32 "
        "{%0,%1,%2,%3}, {%4,%5,%6,%7}, {%8,%9}, {%0,%1,%2,%3};"
        : "+f"(acc[0]), "+f"(acc[1]), "+f"(acc[2]), "+f"(acc[3])
        : "r"(a[0]), "r"(a[1]), "r"(a[2]), "r"(a[3]), "r"(b0), "r"(b1));
}

// ================= CSR build ==================================================
__global__ void zero_deg_kernel(int N) {
    int t = blockIdx.x * blockDim.x + threadIdx.x;
    if (t < N) g_deg[t] = 0;
}

__global__ void deg_kernel(const int* __restrict__ ei, int E, int Etot) {
    int i = blockIdx.x * blockDim.x + threadIdx.x;
    if (i >= Etot) return;
    int d = (i < E) ? ei[E + i] : (i - E);
    atomicAdd(&g_deg[d], 1);
}

// grid scan stage A: per-block exclusive scan + block sums
__global__ __launch_bounds__(1024) void scanA_kernel(int N) {
    __shared__ int wsum[32];
    const int i = blockIdx.x * 1024 + threadIdx.x;
    const int lane = threadIdx.x & 31, wid = threadIdx.x >> 5;
    int v = (i < N) ? g_deg[i] : 0;
    int s = v;
    #pragma unroll
    for (int off = 1; off < 32; off <<= 1) {
        int t = __shfl_up_sync(0xffffffffu, s, off);
        if (lane >= off) s += t;
    }
    if (lane == 31) wsum[wid] = s;
    __syncthreads();
    if (wid == 0) {
        int ws = wsum[lane];
        #pragma unroll
        for (int off = 1; off < 32; off <<= 1) {
            int t = __shfl_up_sync(0xffffffffu, ws, off);
            if (lane >= off) ws += t;
        }
        wsum[lane] = ws;
    }
    __syncthreads();
    int excl = s - v + (wid ? wsum[wid - 1] : 0);
    if (i < N) g_rowptr[i] = excl;
    if (threadIdx.x == 1023) g_bsum[blockIdx.x] = excl + v;
}

// stage B: exclusive scan of block sums (single block, nb <= 128)
__global__ void scanB_kernel(int nb) {
    __shared__ int sh[128];
    const int t = threadIdx.x;
    int v = (t < nb) ? g_bsum[t] : 0;
    sh[t] = v;
    __syncthreads();
    for (int off = 1; off < 128; off <<= 1) {
        int x = (t >= off) ? sh[t - off] : 0;
        __syncthreads();
        sh[t] += x;
        __syncthreads();
    }
    g_bsum[t] = sh[t] - v;
}

// stage C: add block offsets, init cursors
__global__ __launch_bounds__(1024) void scanC_kernel(int N, int Etot) {
    int i = blockIdx.x * 1024 + threadIdx.x;
    if (i < N) {
        int rp = g_rowptr[i] + g_bsum[blockIdx.x];
        g_rowptr[i] = rp;
        g_cur[i]    = rp;
    }
    if (i == 0) g_rowptr[N] = Etot;
}

__global__ void scatter_kernel(const int* __restrict__ ei, int E, int Etot) {
    int i = blockIdx.x * blockDim.x + threadIdx.x;
    if (i >= Etot) return;
    int s, d;
    if (i < E) { s = ei[i]; d = ei[E + i]; }
    else       { s = d = i - E; }
    int pos = atomicAdd(&g_cur[d], 1);
    g_csr_se[pos] = make_int2(s, i);
    g_pos[i] = pos;                          // coalesced (thread i -> edge i)
}

// ---------------- self-loop attr: per-dst gathered mean ----------------------
__global__ void pre_csr_kernel(const float* __restrict__ ea, int E, int N) {
    const int lane = threadIdx.x & 31;
    const int d = blockIdx.x * 8 + (threadIdx.x >> 5);
    if (d >= N) return;
    const int rp0 = g_rowptr[d], rp1 = g_rowptr[d + 1];
    float s = 0.f;
    int cnt = 0;
    for (int e = rp0; e < rp1; ++e) {
        int eid = g_csr_se[e].y;
        if (eid < E) {
            s += ea[(size_t)eid * FE + lane];
            ++cnt;
        }
    }
    g_loop[(size_t)d * FE + lane] = s / (float)max(cnt, 1);
}

// ---------------- node linear transforms via 3xTF32 tensor MMA ---------------
template<int IN, bool FROM_OUT>
__global__ __launch_bounds__(256) void lin_mma_kernel(
        const float* __restrict__ inp,
        const float* __restrict__ Wl, const float* __restrict__ bl,
        const float* __restrict__ Wr, const float* __restrict__ br,
        const float* __restrict__ prevBias, int N) {
    constexpr int KC = 16;
    __shared__ uint XsH[64][20], XsL[64][20];
    __shared__ uint WsH[KC][132], WsL[KC][132];

    const int t = threadIdx.x;
    const int nb = blockIdx.x * 64;
    const int lane = t & 31;
    const int w = t >> 5;
    const int mt = w & 3;
    const int half = w >> 2;
    const int g = lane >> 2, c = lane & 3;

    float acc[8][4];
    #pragma unroll
    for (int nt = 0; nt < 8; ++nt) {
        acc[nt][0] = acc[nt][1] = acc[nt][2] = acc[nt][3] = 0.f;
    }

    for (int kc = 0; kc < IN; kc += KC) {
        __syncthreads();
        for (int idx = t; idx < 64 * KC; idx += 256) {
            int row = idx / KC, col = idx - row * KC;
            int node = nb + row;
            float v = 0.f;
            if (node < N) {
                int j = kc + col;
                if (FROM_OUT) v = fmaxf(g_out[(size_t)node * HID + j] + prevBias[j], 0.f);
                else          v = inp[(size_t)node * IN + j];
            }
            uint hb, lb; tf32_split(v, hb, lb);
            XsH[row][col] = hb; XsL[row][col] = lb;
        }
        for (int idx = t; idx < KC * 128; idx += 256) {
            int row = idx >> 7, col = idx & 127;
            int k = kc + row;
            float v = (col < HID) ? Wl[k * HID + col] : Wr[k * HID + (col - HID)];
            uint hb, lb; tf32_split(v, hb, lb);
            WsH[row][col] = hb; WsL[row][col] = lb;
        }
        __syncthreads();
        #pragma unroll
        for (int kk = 0; kk < KC; kk += 8) {
            uint aH[4], aL[4];
            aH[0] = XsH[mt * 16 + g    ][kk + c];
            aH[1] = XsH[mt * 16 + g + 8][kk + c];
            aH[2] = XsH[mt * 16 + g    ][kk + c + 4];
            aH[3] = XsH[mt * 16 + g + 8][kk + c + 4];
            aL[0] = XsL[mt * 16 + g    ][kk + c];
            aL[1] = XsL[mt * 16 + g + 8][kk + c];
            aL[2] = XsL[mt * 16 + g    ][kk + c + 4];
            aL[3] = XsL[mt * 16 + g + 8][kk + c + 4];
            #pragma unroll
            for (int nt = 0; nt < 8; ++nt) {
                int col = half * 64 + nt * 8 + g;
                uint bH0 = WsH[kk + c    ][col];
                uint bH1 = WsH[kk + c + 4][col];
                uint bL0 = WsL[kk + c    ][col];
                uint bL1 = WsL[kk + c + 4][col];
                mma_tf32(acc[nt], aH, bH0, bH1);
                mma_tf32(acc[nt], aL, bH0, bH1);
                mma_tf32(acc[nt], aH, bL0, bL1);
            }
        }
    }

    const float* bias = half ? br : bl;
    float2* dst2 = reinterpret_cast<float2*>(half ? g_xr : g_xl);
    const int m0 = nb + mt * 16 + g;
    const int m1 = m0 + 8;
    #pragma unroll
    for (int nt = 0; nt < 8; ++nt) {
        int colL = nt * 8 + 2 * c;
        float bx = bias[colL], by = bias[colL + 1];
        if (m0 < N) dst2[(size_t)m0 * 32 + nt * 4 + c] = make_float2(acc[nt][0] + bx, acc[nt][1] + by);
        if (m1 < N) dst2[(size_t)m1 * 32 + nt * 4 + c] = make_float2(acc[nt][2] + bx, acc[nt][3] + by);
    }
}

// ---------------- edge pass A: tensor-core e-GEMM + logits -------------------
// Iterates in ORIGINAL edge order (sequential ea/ei/g_pos reads); writes
// exp(logit) directly into its CSR slot via g_pos (scattered L2 store).
__global__ __launch_bounds__(256) void edgeA_kernel(
        const int* __restrict__ ei, const float* __restrict__ ea,
        const float* __restrict__ We, const float* __restrict__ att,
        int E, int N) {
    __shared__ uint Wes[32 * 68];            // tf32-converted We, padded rows

    const int t = threadIdx.x;
    for (int idx = t; idx < 32 * 64; idx += 256) {
        int row = idx >> 6, col = idx & 63;
        Wes[row * 68 + col] = to_tf32(We[idx]);
    }
    __syncthreads();

    const int lane = t & 31;
    const int w = t >> 5;
    const int g = lane >> 2;                 // row group 0..7
    const int c = lane & 3;                  // col-in-group 0..3
    const int Etot = E + N;
    const int nTiles = (Etot + 15) >> 4;
    const int gw = blockIdx.x * 8 + w;
    const int gws = gridDim.x * 8;

    const float2* xl2 = reinterpret_cast<const float2*>(g_xl);
    const float2* xr2 = reinterpret_cast<const float2*>(g_xr);
    const float2* att2 = reinterpret_cast<const float2*>(att);

    for (int tile = gw; tile < nTiles; tile += gws) {
        const int i0 = tile << 4;
        const int rowA = i0 + g;             // edge id for this lane's rows
        const int rowB = i0 + g + 8;

        int sA = 0, dA = 0, sB = 0, dB = 0;
        const float *pA = ea, *pB = ea;
        if (rowA < E)         { sA = ei[rowA]; dA = ei[E + rowA]; pA = ea + (size_t)rowA * FE; }
        else if (rowA < Etot) { sA = dA = rowA - E; pA = g_loop + (size_t)sA * FE; }
        if (rowB < E)         { sB = ei[rowB]; dB = ei[E + rowB]; pB = ea + (size_t)rowB * FE; }
        else if (rowB < Etot) { sB = dB = rowB - E; pB = g_loop + (size_t)sB * FE; }

        uint afr[4][4];
        #pragma unroll
        for (int ks = 0; ks < 4; ++ks) {
            afr[ks][0] = to_tf32(pA[ks * 8 + c]);
            afr[ks][1] = to_tf32(pB[ks * 8 + c]);
            afr[ks][2] = to_tf32(pA[ks * 8 + c + 4]);
            afr[ks][3] = to_tf32(pB[ks * 8 + c + 4]);
        }

        float partA = 0.f, partB = 0.f;
        #pragma unroll
        for (int nt = 0; nt < 8; ++nt) {
            float acc[4] = {0.f, 0.f, 0.f, 0.f};
            #pragma unroll
            for (int ks = 0; ks < 4; ++ks) {
                uint b0 = Wes[(ks * 8 + c)     * 68 + nt * 8 + g];
                uint b1 = Wes[(ks * 8 + c + 4) * 68 + nt * 8 + g];
                mma_tf32(acc, afr[ks], b0, b1);
            }
            float2 xlA = xl2[(size_t)sA * 32 + nt * 4 + c];
            float2 xrA = xr2[(size_t)dA * 32 + nt * 4 + c];
            float2 xlB = xl2[(size_t)sB * 32 + nt * 4 + c];
            float2 xrB = xr2[(size_t)dB * 32 + nt * 4 + c];
            float u0 = acc[0] + xlA.x + xrA.x;
            float u1 = acc[1] + xlA.y + xrA.y;
            float u2 = acc[2] + xlB.x + xrB.x;
            float u3 = acc[3] + xlB.y + xrB.y;
            u0 = fmaxf(u0, 0.f) + 0.2f * fminf(u0, 0.f);
            u1 = fmaxf(u1, 0.f) + 0.2f * fminf(u1, 0.f);
            u2 = fmaxf(u2, 0.f) + 0.2f * fminf(u2, 0.f);
            u3 = fmaxf(u3, 0.f) + 0.2f * fminf(u3, 0.f);
            float2 av = att2[nt * 4 + c];
            partA = fmaf(u0, av.x, fmaf(u1, av.y, partA));
            partB = fmaf(u2, av.x, fmaf(u3, av.y, partB));
        }
        partA += __shfl_xor_sync(0xffffffffu, partA, 1);
        partA += __shfl_xor_sync(0xffffffffu, partA, 2);
        partB += __shfl_xor_sync(0xffffffffu, partB, 1);
        partB += __shfl_xor_sync(0xffffffffu, partB, 2);
        if (c == 0) {
            if (rowA < Etot) g_exc[g_pos[rowA]] = __expf(partA);
            if (rowB < Etot) g_exc[g_pos[rowB]] = __expf(partB);
        }
    }
}

// ---------------- edge pass B: per-dst softmax-normalize + aggregate ---------
__global__ __launch_bounds__(256) void edgeB_kernel(int N) {
    const int lane = threadIdx.x & 31;
    const int d = blockIdx.x * 8 + (threadIdx.x >> 5);
    if (d >= N) return;
    const int rp0 = g_rowptr[d], rp1 = g_rowptr[d + 1];

    // denominator: sequential reads of g_exc over the segment
    float den = 0.f;
    for (int e = rp0 + lane; e < rp1; e += 32) den += g_exc[e];
    #pragma unroll
    for (int off = 16; off > 0; off >>= 1)
        den += __shfl_xor_sync(0xffffffffu, den, off);
    const float inv = 1.f / den;

    const float2* xl2 = reinterpret_cast<const float2*>(g_xl);
    float ax = 0.f, ay = 0.f;
    if (rp0 < rp1) {
        int src = g_csr_se[rp0].x;
        float wgt = g_exc[rp0];
        for (int e = rp0 + 1; e <= rp1; ++e) {
            int nsrc = 0; float nw = 0.f;
            if (e < rp1) { nsrc = g_csr_se[e].x; nw = g_exc[e]; }
            float2 xv = xl2[(size_t)src * 32 + lane];
            ax = fmaf(wgt, xv.x, ax);
            ay = fmaf(wgt, xv.y, ay);
            src = nsrc; wgt = nw;
        }
    }
    float2* out2 = reinterpret_cast<float2*>(g_out);
    out2[(size_t)d * 32 + lane] = make_float2(ax * inv, ay * inv);
}

// ---------------- kernel: final MLP at node_idx ------------------------------
__global__ void fin_kernel(const int* __restrict__ idx, const float* __restrict__ bias2,
                           const float* __restrict__ y,
                           const float* __restrict__ W0, const float* __restrict__ b0,
                           const float* __restrict__ W1, const float* __restrict__ b1,
                           const float* __restrict__ W2, const float* __restrict__ b2,
                           float* __restrict__ dout, int M, int rf) {
    __shared__ float sh[4][64];
    __shared__ float sz[4][32];
    const int w = threadIdx.x >> 5, lane = threadIdx.x & 31;
    const int m = blockIdx.x * 4 + w;
    if (m >= M) return;
    const int v = idx[m];

    float h0 = fmaxf(g_out[(size_t)v * HID + lane]      + bias2[lane],      0.f);
    float h1 = fmaxf(g_out[(size_t)v * HID + 32 + lane] + bias2[32 + lane], 0.f);
    sh[w][lane] = h0; sh[w][32 + lane] = h1;
    __syncwarp();

    int k = v / rf;
    float y0 = y[2 * k], y1 = y[2 * k + 1];
    float q0 = fmaxf(y0 * W0[0] + y1 * W0[2] + b0[0], 0.f);
    float q1 = fmaxf(y0 * W0[1] + y1 * W0[3] + b0[1], 0.f);

    float z = b1[lane];
    #pragma unroll
    for (int j = 0; j < 64; ++j) z += sh[w][j] * W1[j * 32 + lane];
    z += q0 * W1[64 * 32 + lane] + q1 * W1[65 * 32 + lane];
    z = fmaxf(z, 0.f);
    sz[w][lane] = z;
    __syncwarp();

    float o = b2[lane];
    #pragma unroll
    for (int j = 0; j < 32; ++j) o += sz[w][j] * W2[j * 32 + lane];
    dout[m * 32 + lane] = o;
}

// ---------------- launch ------------------------------------------------------
extern "C" void kernel_launch(void* const* d_in, const int* in_sizes, int n_in,
                              void* d_out, int out_size) {
    const float* x    = (const float*)d_in[0];
    const float* ea   = (const float*)d_in[1];
    const float* y    = (const float*)d_in[2];
    const float* Wl1  = (const float*)d_in[3];
    const float* bl1  = (const float*)d_in[4];
    const float* Wr1  = (const float*)d_in[5];
    const float* br1  = (const float*)d_in[6];
    const float* We1  = (const float*)d_in[7];
    const float* att1 = (const float*)d_in[8];
    const float* bias1= (const float*)d_in[9];
    const float* Wl2  = (const float*)d_in[10];
    const float* bl2  = (const float*)d_in[11];
    const float* Wr2  = (const float*)d_in[12];
    const float* br2  = (const float*)d_in[13];
    const float* We2  = (const float*)d_in[14];
    const float* att2 = (const float*)d_in[15];
    const float* bias2= (const float*)d_in[16];
    const float* W0   = (const float*)d_in[17];
    const float* b0   = (const float*)d_in[18];
    const float* W1   = (const float*)d_in[19];
    const float* b1   = (const float*)d_in[20];
    const float* W2   = (const float*)d_in[21];
    const float* b2   = (const float*)d_in[22];
    const int*   ei   = (const int*)  d_in[23];
    const int*   nidx = (const int*)  d_in[24];

    const int N    = in_sizes[0] / FN;
    const int E    = in_sizes[23] / 2;
    const int Etot = E + N;
    const int M    = in_sizes[24];
    const int NG   = in_sizes[2] / 2;
    const int rf   = N / NG;

    const int EBLK = (Etot + 255) / 256;
    const int NWRP = (N + 7) / 8;        // warp-per-node kernels
    const int NB1K = (N + 1023) / 1024;  // 1024-thread node kernels

    // ---- CSR build + self-loop mean ----
    zero_deg_kernel<<<(N + 255) / 256, 256>>>(N);
    deg_kernel     <<<EBLK, 256>>>(ei, E, Etot);
    scanA_kernel   <<<NB1K, 1024>>>(N);
    scanB_kernel   <<<1, 128>>>(NB1K);
    scanC_kernel   <<<NB1K, 1024>>>(N, Etot);
    scatter_kernel <<<EBLK, 256>>>(ei, E, Etot);
    pre_csr_kernel <<<NWRP, 256>>>(ea, E, N);

    // ---- layer 1 ----
    lin_mma_kernel<FN, false><<<(N + 63) / 64, 256>>>(x, Wl1, bl1, Wr1, br1, nullptr, N);
    edgeA_kernel<<<2048, 256>>>(ei, ea, We1, att1, E, N);
    edgeB_kernel<<<NWRP, 256>>>(N);

    // ---- layer 2 ----
    lin_mma_kernel<HID, true><<<(N + 63) / 64, 256>>>(x, Wl2, bl2, Wr2, br2, bias1, N);
    edgeA_kernel<<<2048, 256>>>(ei, ea, We2, att2, E, N);
    edgeB_kernel<<<NWRP, 256>>>(N);

    // ---- final MLP at node_idx ----
    fin_kernel<<<(M + 3) / 4, 128>>>(nidx, bias2, y, W0, b0, W1, b1, W2, b2,
                                     (float*)d_out, M, rf);
}

// round 7
// speedup vs baseline: 1.2134x; 1.2134x over previous
#include <cuda_runtime.h>
#include <cuda_fp16.h>
#include <cstddef>

typedef unsigned long long ull;
typedef unsigned int uint;

// ---------------- problem constants (shapes fixed by the dataset) -----------
#define MAXN 100000
#define MAXE 1600000
#define MAXET (MAXE + MAXN)
#define MAXETP (MAXET + 16)   // padded (edgeA tile overrun reads zeros)
#define FN   128     // node feature dim (layer1 input)
#define FE   32      // edge feature dim
#define HID  64

// ---------------- device scratch (static: no allocation allowed) ------------
__device__ float  g_xl  [MAXN * HID];       // source-side transform
__device__ float  g_xr  [MAXN * HID];       // target-side transform
__device__ float  g_exc [MAXETP];           // exp(logit), CSR slot order
__device__ float  g_out [MAXN * HID];       // layer output
__device__ int    g_deg [MAXN];             // zero at entry (restored by fin)
__device__ int    g_rowptr[MAXN + 1];
__device__ int    g_cur [MAXN];
__device__ int    g_bsum[128];
__device__ int    g_csr_src[MAXETP];        // src per CSR slot
__device__ int    g_csr_dst[MAXETP];        // dst per CSR slot
__device__ __align__(16) __half g_eap[(size_t)MAXETP * FE];  // permuted fp16 edge attrs

// ---------------- small helpers ---------------------------------------------
__device__ __forceinline__ uint to_tf32(float f) {
    uint r; asm("cvt.rna.tf32.f32 %0, %1;" : "=r"(r) : "f"(f)); return r;
}
__device__ __forceinline__ void tf32_split(float v, uint& hb, uint& lb) {
    asm("cvt.rna.tf32.f32 %0, %1;" : "=r"(hb) : "f"(v));
    float hf = __uint_as_float(hb);
    asm("cvt.rna.tf32.f32 %0, %1;" : "=r"(lb) : "f"(v - hf));
}
__device__ __forceinline__ void mma_tf32(float acc[4], const uint a[4], uint b0, uint b1) {
    asm volatile(
        "mma.sync.aligned.m16n8k8.row.col.f32.tf32.tf32.f32 "
        "{%0,%1,%2,%3}, {%4,%5,%6,%7}, {%8,%9}, {%0,%1,%2,%3};"
        : "+f"(acc[0]), "+f"(acc[1]), "+f"(acc[2]), "+f"(acc[3])
        : "r"(a[0]), "r"(a[1]), "r"(a[2]), "r"(a[3]), "r"(b0), "r"(b1));
}

// ================= CSR build ==================================================
// g_deg is zero on entry (zero-initialized at load; re-zeroed by fin_kernel).
__global__ void deg_kernel(const int* __restrict__ ei, int E) {
    int i = blockIdx.x * blockDim.x + threadIdx.x;
    if (i >= E) return;
    atomicAdd(&g_deg[ei[E + i]], 1);
}

// grid scan stage A: per-block exclusive scan + block sums (deg+1: self loop)
__global__ __launch_bounds__(1024) void scanA_kernel(int N) {
    __shared__ int wsum[32];
    const int i = blockIdx.x * 1024 + threadIdx.x;
    const int lane = threadIdx.x & 31, wid = threadIdx.x >> 5;
    int v = (i < N) ? (g_deg[i] + 1) : 0;
    int s = v;
    #pragma unroll
    for (int off = 1; off < 32; off <<= 1) {
        int t = __shfl_up_sync(0xffffffffu, s, off);
        if (lane >= off) s += t;
    }
    if (lane == 31) wsum[wid] = s;
    __syncthreads();
    if (wid == 0) {
        int ws = wsum[lane];
        #pragma unroll
        for (int off = 1; off < 32; off <<= 1) {
            int t = __shfl_up_sync(0xffffffffu, ws, off);
            if (lane >= off) ws += t;
        }
        wsum[lane] = ws;
    }
    __syncthreads();
    int excl = s - v + (wid ? wsum[wid - 1] : 0);
    if (i < N) g_rowptr[i] = excl;
    if (threadIdx.x == 1023) g_bsum[blockIdx.x] = excl + v;
}

__global__ void scanB_kernel(int nb) {
    __shared__ int sh[128];
    const int t = threadIdx.x;
    int v = (t < nb) ? g_bsum[t] : 0;
    sh[t] = v;
    __syncthreads();
    for (int off = 1; off < 128; off <<= 1) {
        int x = (t >= off) ? sh[t - off] : 0;
        __syncthreads();
        sh[t] += x;
        __syncthreads();
    }
    g_bsum[t] = sh[t] - v;
}

__global__ __launch_bounds__(1024) void scanC_kernel(int N, int Etot) {
    int i = blockIdx.x * 1024 + threadIdx.x;
    if (i < N) {
        int rp = g_rowptr[i] + g_bsum[blockIdx.x];
        g_rowptr[i] = rp;
        g_cur[i]    = rp;
    }
    if (i == 0) g_rowptr[N] = Etot;
}

// scatter + permute + fp16-convert edge attrs into CSR slot order.
// Real edges fill slots [rp0, rp1-1); slot rp1-1 is reserved for the self loop.
__global__ void scatter_kernel(const int* __restrict__ ei, const float* __restrict__ ea, int E) {
    int i = blockIdx.x * blockDim.x + threadIdx.x;
    if (i >= E) return;
    int s = ei[i], d = ei[E + i];
    int pos = atomicAdd(&g_cur[d], 1);
    g_csr_src[pos] = s;
    g_csr_dst[pos] = d;
    const float4* r4 = reinterpret_cast<const float4*>(ea) + (size_t)i * 8;
    __half2* dst = reinterpret_cast<__half2*>(g_eap + (size_t)pos * FE);
    #pragma unroll
    for (int q = 0; q < 8; ++q) {
        float4 v = r4[q];
        dst[2 * q]     = __floats2half2_rn(v.x, v.y);
        dst[2 * q + 1] = __floats2half2_rn(v.z, v.w);
    }
}

// ---------------- self-loop attr: sequential per-segment mean ----------------
__global__ void pre_csr_kernel(int N) {
    const int lane = threadIdx.x & 31;
    const int d = blockIdx.x * 8 + (threadIdx.x >> 5);
    if (d >= N) return;
    const int rp0 = g_rowptr[d], rp1 = g_rowptr[d + 1];
    const int last = rp1 - 1;                // self-loop slot
    float s = 0.f;
    int e = rp0;
    for (; e + 4 <= last; e += 4) {
        float a0 = __half2float(g_eap[(size_t)(e + 0) * FE + lane]);
        float a1 = __half2float(g_eap[(size_t)(e + 1) * FE + lane]);
        float a2 = __half2float(g_eap[(size_t)(e + 2) * FE + lane]);
        float a3 = __half2float(g_eap[(size_t)(e + 3) * FE + lane]);
        s += (a0 + a1) + (a2 + a3);
    }
    for (; e < last; ++e) s += __half2float(g_eap[(size_t)e * FE + lane]);
    float mean = s / (float)max(last - rp0, 1);
    g_eap[(size_t)last * FE + lane] = __float2half_rn(mean);
    if (lane == 0) { g_csr_src[last] = d; g_csr_dst[last] = d; }
}

// ---------------- node linear transforms via 3xTF32 tensor MMA ---------------
template<int IN, bool FROM_OUT>
__global__ __launch_bounds__(256) void lin_mma_kernel(
        const float* __restrict__ inp,
        const float* __restrict__ Wl, const float* __restrict__ bl,
        const float* __restrict__ Wr, const float* __restrict__ br,
        const float* __restrict__ prevBias, int N) {
    constexpr int KC = 16;
    __shared__ uint XsH[64][20], XsL[64][20];
    __shared__ uint WsH[KC][132], WsL[KC][132];

    const int t = threadIdx.x;
    const int nb = blockIdx.x * 64;
    const int lane = t & 31;
    const int w = t >> 5;
    const int mt = w & 3;
    const int half = w >> 2;
    const int g = lane >> 2, c = lane & 3;

    float acc[8][4];
    #pragma unroll
    for (int nt = 0; nt < 8; ++nt) {
        acc[nt][0] = acc[nt][1] = acc[nt][2] = acc[nt][3] = 0.f;
    }

    for (int kc = 0; kc < IN; kc += KC) {
        __syncthreads();
        for (int idx = t; idx < 64 * KC; idx += 256) {
            int row = idx / KC, col = idx - row * KC;
            int node = nb + row;
            float v = 0.f;
            if (node < N) {
                int j = kc + col;
                if (FROM_OUT) v = fmaxf(g_out[(size_t)node * HID + j] + prevBias[j], 0.f);
                else          v = inp[(size_t)node * IN + j];
            }
            uint hb, lb; tf32_split(v, hb, lb);
            XsH[row][col] = hb; XsL[row][col] = lb;
        }
        for (int idx = t; idx < KC * 128; idx += 256) {
            int row = idx >> 7, col = idx & 127;
            int k = kc + row;
            float v = (col < HID) ? Wl[k * HID + col] : Wr[k * HID + (col - HID)];
            uint hb, lb; tf32_split(v, hb, lb);
            WsH[row][col] = hb; WsL[row][col] = lb;
        }
        __syncthreads();
        #pragma unroll
        for (int kk = 0; kk < KC; kk += 8) {
            uint aH[4], aL[4];
            aH[0] = XsH[mt * 16 + g    ][kk + c];
            aH[1] = XsH[mt * 16 + g + 8][kk + c];
            aH[2] = XsH[mt * 16 + g    ][kk + c + 4];
            aH[3] = XsH[mt * 16 + g + 8][kk + c + 4];
            aL[0] = XsL[mt * 16 + g    ][kk + c];
            aL[1] = XsL[mt * 16 + g + 8][kk + c];
            aL[2] = XsL[mt * 16 + g    ][kk + c + 4];
            aL[3] = XsL[mt * 16 + g + 8][kk + c + 4];
            #pragma unroll
            for (int nt = 0; nt < 8; ++nt) {
                int col = half * 64 + nt * 8 + g;
                uint bH0 = WsH[kk + c    ][col];
                uint bH1 = WsH[kk + c + 4][col];
                uint bL0 = WsL[kk + c    ][col];
                uint bL1 = WsL[kk + c + 4][col];
                mma_tf32(acc[nt], aH, bH0, bH1);
                mma_tf32(acc[nt], aL, bH0, bH1);
                mma_tf32(acc[nt], aH, bL0, bL1);
            }
        }
    }

    const float* bias = half ? br : bl;
    float2* dst2 = reinterpret_cast<float2*>(half ? g_xr : g_xl);
    const int m0 = nb + mt * 16 + g;
    const int m1 = m0 + 8;
    #pragma unroll
    for (int nt = 0; nt < 8; ++nt) {
        int colL = nt * 8 + 2 * c;
        float bx = bias[colL], by = bias[colL + 1];
        if (m0 < N) dst2[(size_t)m0 * 32 + nt * 4 + c] = make_float2(acc[nt][0] + bx, acc[nt][1] + by);
        if (m1 < N) dst2[(size_t)m1 * 32 + nt * 4 + c] = make_float2(acc[nt][2] + bx, acc[nt][3] + by);
    }
}

// ---------------- edge pass A: tensor-core e-GEMM + logits (CSR order) -------
// All edge-side reads are sequential (g_eap, g_csr_src/dst); exp(logit) stored
// sequentially to g_exc. Padded arrays make the tail branch-free (zeros).
__global__ __launch_bounds__(256) void edgeA_kernel(
        const float* __restrict__ We, const float* __restrict__ att,
        int Etot) {
    __shared__ uint Wes[32 * 68];            // tf32-converted We, padded rows

    const int t = threadIdx.x;
    for (int idx = t; idx < 32 * 64; idx += 256) {
        int row = idx >> 6, col = idx & 63;
        Wes[row * 68 + col] = to_tf32(We[idx]);
    }
    __syncthreads();

    const int lane = t & 31;
    const int w = t >> 5;
    const int g = lane >> 2;                 // row group 0..7
    const int c = lane & 3;                  // col-in-group 0..3
    const int nTiles = (Etot + 15) >> 4;
    const int gw = blockIdx.x * 8 + w;
    const int gws = gridDim.x * 8;

    const float2* xl2 = reinterpret_cast<const float2*>(g_xl);
    const float2* xr2 = reinterpret_cast<const float2*>(g_xr);
    const float2* att2 = reinterpret_cast<const float2*>(att);

    for (int tile = gw; tile < nTiles; tile += gws) {
        const int i0 = tile << 4;
        const int rowA = i0 + g;             // CSR slot
        const int rowB = i0 + g + 8;

        const int sA = g_csr_src[rowA], dA = g_csr_dst[rowA];
        const int sB = g_csr_src[rowB], dB = g_csr_dst[rowB];
        const __half* pA = g_eap + (size_t)rowA * FE;
        const __half* pB = g_eap + (size_t)rowB * FE;

        uint afr[4][4];
        #pragma unroll
        for (int ks = 0; ks < 4; ++ks) {
            afr[ks][0] = to_tf32(__half2float(pA[ks * 8 + c]));
            afr[ks][1] = to_tf32(__half2float(pB[ks * 8 + c]));
            afr[ks][2] = to_tf32(__half2float(pA[ks * 8 + c + 4]));
            afr[ks][3] = to_tf32(__half2float(pB[ks * 8 + c + 4]));
        }

        float partA = 0.f, partB = 0.f;
        #pragma unroll
        for (int nt = 0; nt < 8; ++nt) {
            float acc[4] = {0.f, 0.f, 0.f, 0.f};
            #pragma unroll
            for (int ks = 0; ks < 4; ++ks) {
                uint b0 = Wes[(ks * 8 + c)     * 68 + nt * 8 + g];
                uint b1 = Wes[(ks * 8 + c + 4) * 68 + nt * 8 + g];
                mma_tf32(acc, afr[ks], b0, b1);
            }
            float2 xlA = xl2[(size_t)sA * 32 + nt * 4 + c];
            float2 xrA = xr2[(size_t)dA * 32 + nt * 4 + c];
            float2 xlB = xl2[(size_t)sB * 32 + nt * 4 + c];
            float2 xrB = xr2[(size_t)dB * 32 + nt * 4 + c];
            float u0 = acc[0] + xlA.x + xrA.x;
            float u1 = acc[1] + xlA.y + xrA.y;
            float u2 = acc[2] + xlB.x + xrB.x;
            float u3 = acc[3] + xlB.y + xrB.y;
            u0 = fmaxf(u0, 0.f) + 0.2f * fminf(u0, 0.f);
            u1 = fmaxf(u1, 0.f) + 0.2f * fminf(u1, 0.f);
            u2 = fmaxf(u2, 0.f) + 0.2f * fminf(u2, 0.f);
            u3 = fmaxf(u3, 0.f) + 0.2f * fminf(u3, 0.f);
            float2 av = att2[nt * 4 + c];
            partA = fmaf(u0, av.x, fmaf(u1, av.y, partA));
            partB = fmaf(u2, av.x, fmaf(u3, av.y, partB));
        }
        partA += __shfl_xor_sync(0xffffffffu, partA, 1);
        partA += __shfl_xor_sync(0xffffffffu, partA, 2);
        partB += __shfl_xor_sync(0xffffffffu, partB, 1);
        partB += __shfl_xor_sync(0xffffffffu, partB, 2);
        if (c == 0) {
            if (rowA < Etot) g_exc[rowA] = __expf(partA);
            if (rowB < Etot) g_exc[rowB] = __expf(partB);
        }
    }
}

// ---------------- edge pass B: per-dst softmax-normalize + aggregate ---------
__global__ __launch_bounds__(256) void edgeB_kernel(int N) {
    const int lane = threadIdx.x & 31;
    const int d = blockIdx.x * 8 + (threadIdx.x >> 5);
    if (d >= N) return;
    const int rp0 = g_rowptr[d], rp1 = g_rowptr[d + 1];

    float den = 0.f;
    for (int e = rp0 + lane; e < rp1; e += 32) den += g_exc[e];
    #pragma unroll
    for (int off = 16; off > 0; off >>= 1)
        den += __shfl_xor_sync(0xffffffffu, den, off);
    const float inv = 1.f / den;

    const float2* xl2 = reinterpret_cast<const float2*>(g_xl);
    float ax = 0.f, ay = 0.f;
    int e = rp0;
    for (; e + 4 <= rp1; e += 4) {
        int s0 = g_csr_src[e],     s1 = g_csr_src[e + 1];
        int s2 = g_csr_src[e + 2], s3 = g_csr_src[e + 3];
        float w0 = g_exc[e],     w1 = g_exc[e + 1];
        float w2 = g_exc[e + 2], w3 = g_exc[e + 3];
        float2 v0 = xl2[(size_t)s0 * 32 + lane];
        float2 v1 = xl2[(size_t)s1 * 32 + lane];
        float2 v2 = xl2[(size_t)s2 * 32 + lane];
        float2 v3 = xl2[(size_t)s3 * 32 + lane];
        ax = fmaf(w0, v0.x, fmaf(w1, v1.x, fmaf(w2, v2.x, fmaf(w3, v3.x, ax))));
        ay = fmaf(w0, v0.y, fmaf(w1, v1.y, fmaf(w2, v2.y, fmaf(w3, v3.y, ay))));
    }
    for (; e < rp1; ++e) {
        int s = g_csr_src[e];
        float wgt = g_exc[e];
        float2 xv = xl2[(size_t)s * 32 + lane];
        ax = fmaf(wgt, xv.x, ax);
        ay = fmaf(wgt, xv.y, ay);
    }
    float2* out2 = reinterpret_cast<float2*>(g_out);
    out2[(size_t)d * 32 + lane] = make_float2(ax * inv, ay * inv);
}

// ---------------- kernel: final MLP at node_idx (+ restore g_deg = 0) --------
__global__ void fin_kernel(const int* __restrict__ idx, const float* __restrict__ bias2,
                           const float* __restrict__ y,
                           const float* __restrict__ W0, const float* __restrict__ b0,
                           const float* __restrict__ W1, const float* __restrict__ b1,
                           const float* __restrict__ W2, const float* __restrict__ b2,
                           float* __restrict__ dout, int M, int rf, int N) {
    // restore the g_deg == 0 invariant for the next launch
    for (int z = blockIdx.x * blockDim.x + threadIdx.x; z < N; z += gridDim.x * blockDim.x)
        g_deg[z] = 0;

    __shared__ float sh[4][64];
    __shared__ float sz[4][32];
    const int w = threadIdx.x >> 5, lane = threadIdx.x & 31;
    const int m = blockIdx.x * 4 + w;
    if (m >= M) return;
    const int v = idx[m];

    float h0 = fmaxf(g_out[(size_t)v * HID + lane]      + bias2[lane],      0.f);
    float h1 = fmaxf(g_out[(size_t)v * HID + 32 + lane] + bias2[32 + lane], 0.f);
    sh[w][lane] = h0; sh[w][32 + lane] = h1;
    __syncwarp();

    int k = v / rf;
    float y0 = y[2 * k], y1 = y[2 * k + 1];
    float q0 = fmaxf(y0 * W0[0] + y1 * W0[2] + b0[0], 0.f);
    float q1 = fmaxf(y0 * W0[1] + y1 * W0[3] + b0[1], 0.f);

    float z = b1[lane];
    #pragma unroll
    for (int j = 0; j < 64; ++j) z += sh[w][j] * W1[j * 32 + lane];
    z += q0 * W1[64 * 32 + lane] + q1 * W1[65 * 32 + lane];
    z = fmaxf(z, 0.f);
    sz[w][lane] = z;
    __syncwarp();

    float o = b2[lane];
    #pragma unroll
    for (int j = 0; j < 32; ++j) o += sz[w][j] * W2[j * 32 + lane];
    dout[m * 32 + lane] = o;
}

// ---------------- launch ------------------------------------------------------
extern "C" void kernel_launch(void* const* d_in, const int* in_sizes, int n_in,
                              void* d_out, int out_size) {
    const float* x    = (const float*)d_in[0];
    const float* ea   = (const float*)d_in[1];
    const float* y    = (const float*)d_in[2];
    const float* Wl1  = (const float*)d_in[3];
    const float* bl1  = (const float*)d_in[4];
    const float* Wr1  = (const float*)d_in[5];
    const float* br1  = (const float*)d_in[6];
    const float* We1  = (const float*)d_in[7];
    const float* att1 = (const float*)d_in[8];
    const float* bias1= (const float*)d_in[9];
    const float* Wl2  = (const float*)d_in[10];
    const float* bl2  = (const float*)d_in[11];
    const float* Wr2  = (const float*)d_in[12];
    const float* br2  = (const float*)d_in[13];
    const float* We2  = (const float*)d_in[14];
    const float* att2 = (const float*)d_in[15];
    const float* bias2= (const float*)d_in[16];
    const float* W0   = (const float*)d_in[17];
    const float* b0   = (const float*)d_in[18];
    const float* W1   = (const float*)d_in[19];
    const float* b1   = (const float*)d_in[20];
    const float* W2   = (const float*)d_in[21];
    const float* b2   = (const float*)d_in[22];
    const int*   ei   = (const int*)  d_in[23];
    const int*   nidx = (const int*)  d_in[24];

    const int N    = in_sizes[0] / FN;
    const int E    = in_sizes[23] / 2;
    const int Etot = E + N;
    const int M    = in_sizes[24];
    const int NG   = in_sizes[2] / 2;
    const int rf   = N / NG;

    const int EBLK = (E + 255) / 256;
    const int NWRP = (N + 7) / 8;        // warp-per-node kernels
    const int NB1K = (N + 1023) / 1024;  // 1024-thread node kernels

    // ---- CSR build + permuted fp16 edge attrs + self-loop mean ----
    deg_kernel     <<<EBLK, 256>>>(ei, E);
    scanA_kernel   <<<NB1K, 1024>>>(N);
    scanB_kernel   <<<1, 128>>>(NB1K);
    scanC_kernel   <<<NB1K, 1024>>>(N, Etot);
    scatter_kernel <<<EBLK, 256>>>(ei, ea, E);
    pre_csr_kernel <<<NWRP, 256>>>(N);

    // ---- layer 1 ----
    lin_mma_kernel<FN, false><<<(N + 63) / 64, 256>>>(x, Wl1, bl1, Wr1, br1, nullptr, N);
    edgeA_kernel<<<2048, 256>>>(We1, att1, Etot);
    edgeB_kernel<<<NWRP, 256>>>(N);

    // ---- layer 2 ----
    lin_mma_kernel<HID, true><<<(N + 63) / 64, 256>>>(x, Wl2, bl2, Wr2, br2, bias1, N);
    edgeA_kernel<<<2048, 256>>>(We2, att2, Etot);
    edgeB_kernel<<<NWRP, 256>>>(N);

    // ---- final MLP at node_idx (also restores g_deg = 0) ----
    fin_kernel<<<(M + 3) / 4, 128>>>(nidx, bias2, y, W0, b0, W1, b1, W2, b2,
                                     (float*)d_out, M, rf, N);
}

// round 8
// speedup vs baseline: 1.2625x; 1.0405x over previous
#include <cuda_runtime.h>
#include <cuda_fp16.h>
#include <cstddef>

typedef unsigned long long ull;
typedef unsigned int uint;

// ---------------- problem constants (shapes fixed by the dataset) -----------
#define MAXN 100000
#define MAXE 1600000
#define MAXET (MAXE + MAXN)
#define MAXETP (MAXET + 16)   // padded (edgeA tile overrun reads zeros)
#define FN   128     // node feature dim (layer1 input)
#define FE   32      // edge feature dim
#define HID  64

// ---------------- device scratch (static: no allocation allowed) ------------
__device__ float  g_xl  [MAXN * HID];       // source-side transform
__device__ float  g_xr  [MAXN * HID];       // target-side transform
__device__ float  g_exc [MAXETP];           // exp(logit), CSR slot order
__device__ float  g_out [MAXN * HID];       // layer output
__device__ int    g_deg [MAXN];             // zero at entry (restored by fin)
__device__ int    g_rowptr[MAXN + 1];
__device__ int    g_cur [MAXN];
__device__ int    g_bsum[128];
__device__ int    g_csr_src[MAXETP];        // src per CSR slot
__device__ int    g_csr_dst[MAXETP];        // dst per CSR slot
__device__ __align__(16) __half g_eap[(size_t)MAXETP * FE];  // permuted fp16 edge attrs

// ---------------- small helpers ---------------------------------------------
__device__ __forceinline__ void tf32_split(float v, uint& hb, uint& lb) {
    asm("cvt.rna.tf32.f32 %0, %1;" : "=r"(hb) : "f"(v));
    float hf = __uint_as_float(hb);
    asm("cvt.rna.tf32.f32 %0, %1;" : "=r"(lb) : "f"(v - hf));
}
__device__ __forceinline__ void mma_tf32(float acc[4], const uint a[4], uint b0, uint b1) {
    asm volatile(
        "mma.sync.aligned.m16n8k8.row.col.f32.tf32.tf32.f32 "
        "{%0,%1,%2,%3}, {%4,%5,%6,%7}, {%8,%9}, {%0,%1,%2,%3};"
        : "+f"(acc[0]), "+f"(acc[1]), "+f"(acc[2]), "+f"(acc[3])
        : "r"(a[0]), "r"(a[1]), "r"(a[2]), "r"(a[3]), "r"(b0), "r"(b1));
}
__device__ __forceinline__ void mma_f16(float acc[4], uint a0, uint a1, uint a2, uint a3,
                                        uint b0, uint b1) {
    asm volatile(
        "mma.sync.aligned.m16n8k16.row.col.f32.f16.f16.f32 "
        "{%0,%1,%2,%3}, {%4,%5,%6,%7}, {%8,%9}, {%0,%1,%2,%3};"
        : "+f"(acc[0]), "+f"(acc[1]), "+f"(acc[2]), "+f"(acc[3])
        : "r"(a0), "r"(a1), "r"(a2), "r"(a3), "r"(b0), "r"(b1));
}

// ================= CSR build ==================================================
// g_deg is zero on entry (zero-initialized at load; re-zeroed by fin_kernel).
__global__ void deg_kernel(const int* __restrict__ ei, int E) {
    int i = blockIdx.x * blockDim.x + threadIdx.x;
    if (i >= E) return;
    atomicAdd(&g_deg[ei[E + i]], 1);
}

// grid scan stage A: per-block exclusive scan + block sums (deg+1: self loop)
__global__ __launch_bounds__(1024) void scanA_kernel(int N) {
    __shared__ int wsum[32];
    const int i = blockIdx.x * 1024 + threadIdx.x;
    const int lane = threadIdx.x & 31, wid = threadIdx.x >> 5;
    int v = (i < N) ? (g_deg[i] + 1) : 0;
    int s = v;
    #pragma unroll
    for (int off = 1; off < 32; off <<= 1) {
        int t = __shfl_up_sync(0xffffffffu, s, off);
        if (lane >= off) s += t;
    }
    if (lane == 31) wsum[wid] = s;
    __syncthreads();
    if (wid == 0) {
        int ws = wsum[lane];
        #pragma unroll
        for (int off = 1; off < 32; off <<= 1) {
            int t = __shfl_up_sync(0xffffffffu, ws, off);
            if (lane >= off) ws += t;
        }
        wsum[lane] = ws;
    }
    __syncthreads();
    int excl = s - v + (wid ? wsum[wid - 1] : 0);
    if (i < N) g_rowptr[i] = excl;
    if (threadIdx.x == 1023) g_bsum[blockIdx.x] = excl + v;
}

__global__ void scanB_kernel(int nb) {
    __shared__ int sh[128];
    const int t = threadIdx.x;
    int v = (t < nb) ? g_bsum[t] : 0;
    sh[t] = v;
    __syncthreads();
    for (int off = 1; off < 128; off <<= 1) {
        int x = (t >= off) ? sh[t - off] : 0;
        __syncthreads();
        sh[t] += x;
        __syncthreads();
    }
    g_bsum[t] = sh[t] - v;
}

__global__ __launch_bounds__(1024) void scanC_kernel(int N, int Etot) {
    int i = blockIdx.x * 1024 + threadIdx.x;
    if (i < N) {
        int rp = g_rowptr[i] + g_bsum[blockIdx.x];
        g_rowptr[i] = rp;
        g_cur[i]    = rp;
    }
    if (i == 0) g_rowptr[N] = Etot;
}

// scatter + permute + fp16-convert edge attrs into CSR slot order.
// Real edges fill slots [rp0, rp1-1); slot rp1-1 is reserved for the self loop.
__global__ void scatter_kernel(const int* __restrict__ ei, const float* __restrict__ ea, int E) {
    int i = blockIdx.x * blockDim.x + threadIdx.x;
    if (i >= E) return;
    int s = ei[i], d = ei[E + i];
    int pos = atomicAdd(&g_cur[d], 1);
    g_csr_src[pos] = s;
    g_csr_dst[pos] = d;
    const float4* r4 = reinterpret_cast<const float4*>(ea) + (size_t)i * 8;
    __half2* dst = reinterpret_cast<__half2*>(g_eap + (size_t)pos * FE);
    #pragma unroll
    for (int q = 0; q < 8; ++q) {
        float4 v = r4[q];
        dst[2 * q]     = __floats2half2_rn(v.x, v.y);
        dst[2 * q + 1] = __floats2half2_rn(v.z, v.w);
    }
}

// ---------------- self-loop attr: sequential per-segment mean ----------------
__global__ void pre_csr_kernel(int N) {
    const int lane = threadIdx.x & 31;
    const int d = blockIdx.x * 8 + (threadIdx.x >> 5);
    if (d >= N) return;
    const int rp0 = g_rowptr[d], rp1 = g_rowptr[d + 1];
    const int last = rp1 - 1;                // self-loop slot
    float s = 0.f;
    int e = rp0;
    for (; e + 4 <= last; e += 4) {
        float a0 = __half2float(g_eap[(size_t)(e + 0) * FE + lane]);
        float a1 = __half2float(g_eap[(size_t)(e + 1) * FE + lane]);
        float a2 = __half2float(g_eap[(size_t)(e + 2) * FE + lane]);
        float a3 = __half2float(g_eap[(size_t)(e + 3) * FE + lane]);
        s += (a0 + a1) + (a2 + a3);
    }
    for (; e < last; ++e) s += __half2float(g_eap[(size_t)e * FE + lane]);
    float mean = s / (float)max(last - rp0, 1);
    g_eap[(size_t)last * FE + lane] = __float2half_rn(mean);
    if (lane == 0) { g_csr_src[last] = d; g_csr_dst[last] = d; }
}

// ---------------- node linear transforms via 3xTF32 tensor MMA ---------------
template<int IN, bool FROM_OUT>
__global__ __launch_bounds__(256) void lin_mma_kernel(
        const float* __restrict__ inp,
        const float* __restrict__ Wl, const float* __restrict__ bl,
        const float* __restrict__ Wr, const float* __restrict__ br,
        const float* __restrict__ prevBias, int N) {
    constexpr int KC = 16;
    __shared__ uint XsH[64][20], XsL[64][20];
    __shared__ uint WsH[KC][132], WsL[KC][132];

    const int t = threadIdx.x;
    const int nb = blockIdx.x * 64;
    const int lane = t & 31;
    const int w = t >> 5;
    const int mt = w & 3;
    const int half = w >> 2;
    const int g = lane >> 2, c = lane & 3;

    float acc[8][4];
    #pragma unroll
    for (int nt = 0; nt < 8; ++nt) {
        acc[nt][0] = acc[nt][1] = acc[nt][2] = acc[nt][3] = 0.f;
    }

    for (int kc = 0; kc < IN; kc += KC) {
        __syncthreads();
        for (int idx = t; idx < 64 * KC; idx += 256) {
            int row = idx / KC, col = idx - row * KC;
            int node = nb + row;
            float v = 0.f;
            if (node < N) {
                int j = kc + col;
                if (FROM_OUT) v = fmaxf(g_out[(size_t)node * HID + j] + prevBias[j], 0.f);
                else          v = inp[(size_t)node * IN + j];
            }
            uint hb, lb; tf32_split(v, hb, lb);
            XsH[row][col] = hb; XsL[row][col] = lb;
        }
        for (int idx = t; idx < KC * 128; idx += 256) {
            int row = idx >> 7, col = idx & 127;
            int k = kc + row;
            float v = (col < HID) ? Wl[k * HID + col] : Wr[k * HID + (col - HID)];
            uint hb, lb; tf32_split(v, hb, lb);
            WsH[row][col] = hb; WsL[row][col] = lb;
        }
        __syncthreads();
        #pragma unroll
        for (int kk = 0; kk < KC; kk += 8) {
            uint aH[4], aL[4];
            aH[0] = XsH[mt * 16 + g    ][kk + c];
            aH[1] = XsH[mt * 16 + g + 8][kk + c];
            aH[2] = XsH[mt * 16 + g    ][kk + c + 4];
            aH[3] = XsH[mt * 16 + g + 8][kk + c + 4];
            aL[0] = XsL[mt * 16 + g    ][kk + c];
            aL[1] = XsL[mt * 16 + g + 8][kk + c];
            aL[2] = XsL[mt * 16 + g    ][kk + c + 4];
            aL[3] = XsL[mt * 16 + g + 8][kk + c + 4];
            #pragma unroll
            for (int nt = 0; nt < 8; ++nt) {
                int col = half * 64 + nt * 8 + g;
                uint bH0 = WsH[kk + c    ][col];
                uint bH1 = WsH[kk + c + 4][col];
                uint bL0 = WsL[kk + c    ][col];
                uint bL1 = WsL[kk + c + 4][col];
                mma_tf32(acc[nt], aH, bH0, bH1);
                mma_tf32(acc[nt], aL, bH0, bH1);
                mma_tf32(acc[nt], aH, bL0, bL1);
            }
        }
    }

    const float* bias = half ? br : bl;
    float2* dst2 = reinterpret_cast<float2*>(half ? g_xr : g_xl);
    const int m0 = nb + mt * 16 + g;
    const int m1 = m0 + 8;
    #pragma unroll
    for (int nt = 0; nt < 8; ++nt) {
        int colL = nt * 8 + 2 * c;
        float bx = bias[colL], by = bias[colL + 1];
        if (m0 < N) dst2[(size_t)m0 * 32 + nt * 4 + c] = make_float2(acc[nt][0] + bx, acc[nt][1] + by);
        if (m1 < N) dst2[(size_t)m1 * 32 + nt * 4 + c] = make_float2(acc[nt][2] + bx, acc[nt][3] + by);
    }
}

// ---------------- edge pass A: fp16 tensor-core e-GEMM + logits (CSR order) --
// All edge-side reads are sequential; A-fragments load directly from fp16
// g_eap as u32 pairs; We/att fragments live in registers (no smem, no cvt).
__global__ __launch_bounds__(256) void edgeA_kernel(
        const float* __restrict__ We, const float* __restrict__ att,
        int Etot) {
    const int t = threadIdx.x;
    const int lane = t & 31;
    const int w = t >> 5;
    const int g = lane >> 2;                 // row group 0..7
    const int c = lane & 3;                  // col-in-group 0..3
    const int nTiles = (Etot + 15) >> 4;
    const int gw = blockIdx.x * 8 + w;
    const int gws = gridDim.x * 8;

    // preload B fragments (We as fp16) and att pairs into registers
    // b[nt][ks][0] = half2(We[k][n], We[k+1][n]) with k = ks*16 + 2c, n = nt*8+g
    // b[nt][ks][1] = same with k = ks*16 + 2c + 8
    uint breg[8][2][2];
    float2 areg[8];
    #pragma unroll
    for (int nt = 0; nt < 8; ++nt) {
        const int n = nt * 8 + g;
        #pragma unroll
        for (int ks = 0; ks < 2; ++ks) {
            int k0 = ks * 16 + 2 * c;
            __half2 lo = __floats2half2_rn(We[k0 * HID + n],       We[(k0 + 1) * HID + n]);
            __half2 hi = __floats2half2_rn(We[(k0 + 8) * HID + n], We[(k0 + 9) * HID + n]);
            breg[nt][ks][0] = *reinterpret_cast<uint*>(&lo);
            breg[nt][ks][1] = *reinterpret_cast<uint*>(&hi);
        }
        areg[nt] = reinterpret_cast<const float2*>(att)[nt * 4 + c];
    }

    const float2* xl2 = reinterpret_cast<const float2*>(g_xl);
    const float2* xr2 = reinterpret_cast<const float2*>(g_xr);

    for (int tile = gw; tile < nTiles; tile += gws) {
        const int i0 = tile << 4;
        const int rowA = i0 + g;             // CSR slot
        const int rowB = i0 + g + 8;

        const int sA = g_csr_src[rowA], dA = g_csr_dst[rowA];
        const int sB = g_csr_src[rowB], dB = g_csr_dst[rowB];
        const uint* pA = reinterpret_cast<const uint*>(g_eap + (size_t)rowA * FE);
        const uint* pB = reinterpret_cast<const uint*>(g_eap + (size_t)rowB * FE);

        // A fragments: half2 pairs. ks*16+2c (halfs) -> word index ks*8+c
        uint afr[2][4];
        #pragma unroll
        for (int ks = 0; ks < 2; ++ks) {
            afr[ks][0] = pA[ks * 8 + c];
            afr[ks][1] = pB[ks * 8 + c];
            afr[ks][2] = pA[ks * 8 + c + 4];
            afr[ks][3] = pB[ks * 8 + c + 4];
        }

        float partA = 0.f, partB = 0.f;
        #pragma unroll
        for (int nt = 0; nt < 8; ++nt) {
            float acc[4] = {0.f, 0.f, 0.f, 0.f};
            mma_f16(acc, afr[0][0], afr[0][1], afr[0][2], afr[0][3],
                    breg[nt][0][0], breg[nt][0][1]);
            mma_f16(acc, afr[1][0], afr[1][1], afr[1][2], afr[1][3],
                    breg[nt][1][0], breg[nt][1][1]);
            float2 xlA = xl2[(size_t)sA * 32 + nt * 4 + c];
            float2 xrA = xr2[(size_t)dA * 32 + nt * 4 + c];
            float2 xlB = xl2[(size_t)sB * 32 + nt * 4 + c];
            float2 xrB = xr2[(size_t)dB * 32 + nt * 4 + c];
            float u0 = acc[0] + xlA.x + xrA.x;
            float u1 = acc[1] + xlA.y + xrA.y;
            float u2 = acc[2] + xlB.x + xrB.x;
            float u3 = acc[3] + xlB.y + xrB.y;
            u0 = fmaxf(u0, 0.f) + 0.2f * fminf(u0, 0.f);
            u1 = fmaxf(u1, 0.f) + 0.2f * fminf(u1, 0.f);
            u2 = fmaxf(u2, 0.f) + 0.2f * fminf(u2, 0.f);
            u3 = fmaxf(u3, 0.f) + 0.2f * fminf(u3, 0.f);
            partA = fmaf(u0, areg[nt].x, fmaf(u1, areg[nt].y, partA));
            partB = fmaf(u2, areg[nt].x, fmaf(u3, areg[nt].y, partB));
        }
        partA += __shfl_xor_sync(0xffffffffu, partA, 1);
        partA += __shfl_xor_sync(0xffffffffu, partA, 2);
        partB += __shfl_xor_sync(0xffffffffu, partB, 1);
        partB += __shfl_xor_sync(0xffffffffu, partB, 2);
        if (c == 0) {
            if (rowA < Etot) g_exc[rowA] = __expf(partA);
            if (rowB < Etot) g_exc[rowB] = __expf(partB);
        }
    }
}

// ---------------- edge pass B: per-dst softmax-normalize + aggregate ---------
__global__ __launch_bounds__(256) void edgeB_kernel(int N) {
    const int lane = threadIdx.x & 31;
    const int d = blockIdx.x * 8 + (threadIdx.x >> 5);
    if (d >= N) return;
    const int rp0 = g_rowptr[d], rp1 = g_rowptr[d + 1];

    float den = 0.f;
    for (int e = rp0 + lane; e < rp1; e += 32) den += g_exc[e];
    #pragma unroll
    for (int off = 16; off > 0; off >>= 1)
        den += __shfl_xor_sync(0xffffffffu, den, off);
    const float inv = 1.f / den;

    const float2* xl2 = reinterpret_cast<const float2*>(g_xl);
    float ax = 0.f, ay = 0.f;
    int e = rp0;
    for (; e + 4 <= rp1; e += 4) {
        int s0 = g_csr_src[e],     s1 = g_csr_src[e + 1];
        int s2 = g_csr_src[e + 2], s3 = g_csr_src[e + 3];
        float w0 = g_exc[e],     w1 = g_exc[e + 1];
        float w2 = g_exc[e + 2], w3 = g_exc[e + 3];
        float2 v0 = xl2[(size_t)s0 * 32 + lane];
        float2 v1 = xl2[(size_t)s1 * 32 + lane];
        float2 v2 = xl2[(size_t)s2 * 32 + lane];
        float2 v3 = xl2[(size_t)s3 * 32 + lane];
        ax = fmaf(w0, v0.x, fmaf(w1, v1.x, fmaf(w2, v2.x, fmaf(w3, v3.x, ax))));
        ay = fmaf(w0, v0.y, fmaf(w1, v1.y, fmaf(w2, v2.y, fmaf(w3, v3.y, ay))));
    }
    for (; e < rp1; ++e) {
        int s = g_csr_src[e];
        float wgt = g_exc[e];
        float2 xv = xl2[(size_t)s * 32 + lane];
        ax = fmaf(wgt, xv.x, ax);
        ay = fmaf(wgt, xv.y, ay);
    }
    float2* out2 = reinterpret_cast<float2*>(g_out);
    out2[(size_t)d * 32 + lane] = make_float2(ax * inv, ay * inv);
}

// ---------------- kernel: final MLP at node_idx (+ restore g_deg = 0) --------
__global__ void fin_kernel(const int* __restrict__ idx, const float* __restrict__ bias2,
                           const float* __restrict__ y,
                           const float* __restrict__ W0, const float* __restrict__ b0,
                           const float* __restrict__ W1, const float* __restrict__ b1,
                           const float* __restrict__ W2, const float* __restrict__ b2,
                           float* __restrict__ dout, int M, int rf, int N) {
    // restore the g_deg == 0 invariant for the next launch
    for (int z = blockIdx.x * blockDim.x + threadIdx.x; z < N; z += gridDim.x * blockDim.x)
        g_deg[z] = 0;

    __shared__ float sh[4][64];
    __shared__ float sz[4][32];
    const int w = threadIdx.x >> 5, lane = threadIdx.x & 31;
    const int m = blockIdx.x * 4 + w;
    if (m >= M) return;
    const int v = idx[m];

    float h0 = fmaxf(g_out[(size_t)v * HID + lane]      + bias2[lane],      0.f);
    float h1 = fmaxf(g_out[(size_t)v * HID + 32 + lane] + bias2[32 + lane], 0.f);
    sh[w][lane] = h0; sh[w][32 + lane] = h1;
    __syncwarp();

    int k = v / rf;
    float y0 = y[2 * k], y1 = y[2 * k + 1];
    float q0 = fmaxf(y0 * W0[0] + y1 * W0[2] + b0[0], 0.f);
    float q1 = fmaxf(y0 * W0[1] + y1 * W0[3] + b0[1], 0.f);

    float z = b1[lane];
    #pragma unroll
    for (int j = 0; j < 64; ++j) z += sh[w][j] * W1[j * 32 + lane];
    z += q0 * W1[64 * 32 + lane] + q1 * W1[65 * 32 + lane];
    z = fmaxf(z, 0.f);
    sz[w][lane] = z;
    __syncwarp();

    float o = b2[lane];
    #pragma unroll
    for (int j = 0; j < 32; ++j) o += sz[w][j] * W2[j * 32 + lane];
    dout[m * 32 + lane] = o;
}

// ---------------- launch ------------------------------------------------------
extern "C" void kernel_launch(void* const* d_in, const int* in_sizes, int n_in,
                              void* d_out, int out_size) {
    const float* x    = (const float*)d_in[0];
    const float* ea   = (const float*)d_in[1];
    const float* y    = (const float*)d_in[2];
    const float* Wl1  = (const float*)d_in[3];
    const float* bl1  = (const float*)d_in[4];
    const float* Wr1  = (const float*)d_in[5];
    const float* br1  = (const float*)d_in[6];
    const float* We1  = (const float*)d_in[7];
    const float* att1 = (const float*)d_in[8];
    const float* bias1= (const float*)d_in[9];
    const float* Wl2  = (const float*)d_in[10];
    const float* bl2  = (const float*)d_in[11];
    const float* Wr2  = (const float*)d_in[12];
    const float* br2  = (const float*)d_in[13];
    const float* We2  = (const float*)d_in[14];
    const float* att2 = (const float*)d_in[15];
    const float* bias2= (const float*)d_in[16];
    const float* W0   = (const float*)d_in[17];
    const float* b0   = (const float*)d_in[18];
    const float* W1   = (const float*)d_in[19];
    const float* b1   = (const float*)d_in[20];
    const float* W2   = (const float*)d_in[21];
    const float* b2   = (const float*)d_in[22];
    const int*   ei   = (const int*)  d_in[23];
    const int*   nidx = (const int*)  d_in[24];

    const int N    = in_sizes[0] / FN;
    const int E    = in_sizes[23] / 2;
    const int Etot = E + N;
    const int M    = in_sizes[24];
    const int NG   = in_sizes[2] / 2;
    const int rf   = N / NG;

    const int EBLK = (E + 255) / 256;
    const int NWRP = (N + 7) / 8;        // warp-per-node kernels
    const int NB1K = (N + 1023) / 1024;  // 1024-thread node kernels

    // ---- CSR build + permuted fp16 edge attrs + self-loop mean ----
    deg_kernel     <<<EBLK, 256>>>(ei, E);
    scanA_kernel   <<<NB1K, 1024>>>(N);
    scanB_kernel   <<<1, 128>>>(NB1K);
    scanC_kernel   <<<NB1K, 1024>>>(N, Etot);
    scatter_kernel <<<EBLK, 256>>>(ei, ea, E);
    pre_csr_kernel <<<NWRP, 256>>>(N);

    // ---- layer 1 ----
    lin_mma_kernel<FN, false><<<(N + 63) / 64, 256>>>(x, Wl1, bl1, Wr1, br1, nullptr, N);
    edgeA_kernel<<<2048, 256>>>(We1, att1, Etot);
    edgeB_kernel<<<NWRP, 256>>>(N);

    // ---- layer 2 ----
    lin_mma_kernel<HID, true><<<(N + 63) / 64, 256>>>(x, Wl2, bl2, Wr2, br2, bias1, N);
    edgeA_kernel<<<2048, 256>>>(We2, att2, Etot);
    edgeB_kernel<<<NWRP, 256>>>(N);

    // ---- final MLP at node_idx (also restores g_deg = 0) ----
    fin_kernel<<<(M + 3) / 4, 128>>>(nidx, bias2, y, W0, b0, W1, b1, W2, b2,
                                     (float*)d_out, M, rf, N);
}

// round 9
// speedup vs baseline: 1.4047x; 1.1126x over previous
#include <cuda_runtime.h>
#include <cuda_fp16.h>
#include <cstddef>

typedef unsigned long long ull;
typedef unsigned int uint;

// ---------------- problem constants (shapes fixed by the dataset) -----------
#define MAXN 100000
#define MAXE 1600000
#define MAXET (MAXE + MAXN)
#define MAXETP (MAXET + 16)   // padded (edgeA tile overrun reads zeros)
#define FN   128     // node feature dim (layer1 input)
#define FE   32      // edge feature dim
#define HID  64

// ---------------- device scratch (static: no allocation allowed) ------------
__device__ __align__(16) __half g_xlh[MAXN * HID];  // source-side transform (fp16)
__device__ __align__(16) __half g_xrh[MAXN * HID];  // target-side transform (fp16)
__device__ float  g_exc [MAXETP];           // exp(logit), CSR slot order
__device__ float  g_out [MAXN * HID];       // layer output
__device__ int    g_deg [MAXN];             // zero at entry (restored by fin)
__device__ int    g_rowptr[MAXN + 1];
__device__ int    g_cur [MAXN];
__device__ int    g_bsum[128];
__device__ int    g_csr_src[MAXETP];        // src per CSR slot
__device__ int    g_csr_dst[MAXETP];        // dst per CSR slot
__device__ __align__(16) __half g_eap[(size_t)MAXETP * FE];  // permuted fp16 edge attrs

// ---------------- small helpers ---------------------------------------------
__device__ __forceinline__ void tf32_split(float v, uint& hb, uint& lb) {
    asm("cvt.rna.tf32.f32 %0, %1;" : "=r"(hb) : "f"(v));
    float hf = __uint_as_float(hb);
    asm("cvt.rna.tf32.f32 %0, %1;" : "=r"(lb) : "f"(v - hf));
}
__device__ __forceinline__ void mma_tf32(float acc[4], const uint a[4], uint b0, uint b1) {
    asm volatile(
        "mma.sync.aligned.m16n8k8.row.col.f32.tf32.tf32.f32 "
        "{%0,%1,%2,%3}, {%4,%5,%6,%7}, {%8,%9}, {%0,%1,%2,%3};"
        : "+f"(acc[0]), "+f"(acc[1]), "+f"(acc[2]), "+f"(acc[3])
        : "r"(a[0]), "r"(a[1]), "r"(a[2]), "r"(a[3]), "r"(b0), "r"(b1));
}
__device__ __forceinline__ void mma_f16(float acc[4], uint a0, uint a1, uint a2, uint a3,
                                        uint b0, uint b1) {
    asm volatile(
        "mma.sync.aligned.m16n8k16.row.col.f32.f16.f16.f32 "
        "{%0,%1,%2,%3}, {%4,%5,%6,%7}, {%8,%9}, {%0,%1,%2,%3};"
        : "+f"(acc[0]), "+f"(acc[1]), "+f"(acc[2]), "+f"(acc[3])
        : "r"(a0), "r"(a1), "r"(a2), "r"(a3), "r"(b0), "r"(b1));
}
__device__ __forceinline__ float2 h2f2(uint v) {
    __half2 h = *reinterpret_cast<__half2*>(&v);
    return __half22float2(h);
}

// ================= CSR build ==================================================
// g_deg is zero on entry (zero-initialized at load; re-zeroed by fin_kernel).
__global__ void deg_kernel(const int* __restrict__ ei, int E) {
    int i = blockIdx.x * blockDim.x + threadIdx.x;
    if (i >= E) return;
    atomicAdd(&g_deg[ei[E + i]], 1);
}

// grid scan stage A: per-block exclusive scan + block sums (deg+1: self loop)
__global__ __launch_bounds__(1024) void scanA_kernel(int N) {
    __shared__ int wsum[32];
    const int i = blockIdx.x * 1024 + threadIdx.x;
    const int lane = threadIdx.x & 31, wid = threadIdx.x >> 5;
    int v = (i < N) ? (g_deg[i] + 1) : 0;
    int s = v;
    #pragma unroll
    for (int off = 1; off < 32; off <<= 1) {
        int t = __shfl_up_sync(0xffffffffu, s, off);
        if (lane >= off) s += t;
    }
    if (lane == 31) wsum[wid] = s;
    __syncthreads();
    if (wid == 0) {
        int ws = wsum[lane];
        #pragma unroll
        for (int off = 1; off < 32; off <<= 1) {
            int t = __shfl_up_sync(0xffffffffu, ws, off);
            if (lane >= off) ws += t;
        }
        wsum[lane] = ws;
    }
    __syncthreads();
    int excl = s - v + (wid ? wsum[wid - 1] : 0);
    if (i < N) g_rowptr[i] = excl;
    if (threadIdx.x == 1023) g_bsum[blockIdx.x] = excl + v;
}

__global__ void scanB_kernel(int nb) {
    __shared__ int sh[128];
    const int t = threadIdx.x;
    int v = (t < nb) ? g_bsum[t] : 0;
    sh[t] = v;
    __syncthreads();
    for (int off = 1; off < 128; off <<= 1) {
        int x = (t >= off) ? sh[t - off] : 0;
        __syncthreads();
        sh[t] += x;
        __syncthreads();
    }
    g_bsum[t] = sh[t] - v;
}

__global__ __launch_bounds__(1024) void scanC_kernel(int N, int Etot) {
    int i = blockIdx.x * 1024 + threadIdx.x;
    if (i < N) {
        int rp = g_rowptr[i] + g_bsum[blockIdx.x];
        g_rowptr[i] = rp;
        g_cur[i]    = rp;
    }
    if (i == 0) g_rowptr[N] = Etot;
}

// scatter + permute + fp16-convert edge attrs into CSR slot order.
// Real edges fill slots [rp0, rp1-1); slot rp1-1 is reserved for the self loop.
__global__ void scatter_kernel(const int* __restrict__ ei, const float* __restrict__ ea, int E) {
    int i = blockIdx.x * blockDim.x + threadIdx.x;
    if (i >= E) return;
    int s = ei[i], d = ei[E + i];
    int pos = atomicAdd(&g_cur[d], 1);
    g_csr_src[pos] = s;
    g_csr_dst[pos] = d;
    const float4* r4 = reinterpret_cast<const float4*>(ea) + (size_t)i * 8;
    __half2* dst = reinterpret_cast<__half2*>(g_eap + (size_t)pos * FE);
    #pragma unroll
    for (int q = 0; q < 8; ++q) {
        float4 v = r4[q];
        dst[2 * q]     = __floats2half2_rn(v.x, v.y);
        dst[2 * q + 1] = __floats2half2_rn(v.z, v.w);
    }
}

// ---------------- self-loop attr: sequential per-segment mean ----------------
__global__ void pre_csr_kernel(int N) {
    const int lane = threadIdx.x & 31;
    const int d = blockIdx.x * 8 + (threadIdx.x >> 5);
    if (d >= N) return;
    const int rp0 = g_rowptr[d], rp1 = g_rowptr[d + 1];
    const int last = rp1 - 1;                // self-loop slot
    float s = 0.f;
    int e = rp0;
    for (; e + 4 <= last; e += 4) {
        float a0 = __half2float(g_eap[(size_t)(e + 0) * FE + lane]);
        float a1 = __half2float(g_eap[(size_t)(e + 1) * FE + lane]);
        float a2 = __half2float(g_eap[(size_t)(e + 2) * FE + lane]);
        float a3 = __half2float(g_eap[(size_t)(e + 3) * FE + lane]);
        s += (a0 + a1) + (a2 + a3);
    }
    for (; e < last; ++e) s += __half2float(g_eap[(size_t)e * FE + lane]);
    float mean = s / (float)max(last - rp0, 1);
    g_eap[(size_t)last * FE + lane] = __float2half_rn(mean);
    if (lane == 0) { g_csr_src[last] = d; g_csr_dst[last] = d; }
}

// ---------------- node linear transforms via 3xTF32 tensor MMA ---------------
template<int IN, bool FROM_OUT>
__global__ __launch_bounds__(256) void lin_mma_kernel(
        const float* __restrict__ inp,
        const float* __restrict__ Wl, const float* __restrict__ bl,
        const float* __restrict__ Wr, const float* __restrict__ br,
        const float* __restrict__ prevBias, int N) {
    constexpr int KC = 16;
    __shared__ uint XsH[64][20], XsL[64][20];
    __shared__ uint WsH[KC][132], WsL[KC][132];

    const int t = threadIdx.x;
    const int nb = blockIdx.x * 64;
    const int lane = t & 31;
    const int w = t >> 5;
    const int mt = w & 3;
    const int half = w >> 2;
    const int g = lane >> 2, c = lane & 3;

    float acc[8][4];
    #pragma unroll
    for (int nt = 0; nt < 8; ++nt) {
        acc[nt][0] = acc[nt][1] = acc[nt][2] = acc[nt][3] = 0.f;
    }

    for (int kc = 0; kc < IN; kc += KC) {
        __syncthreads();
        for (int idx = t; idx < 64 * KC; idx += 256) {
            int row = idx / KC, col = idx - row * KC;
            int node = nb + row;
            float v = 0.f;
            if (node < N) {
                int j = kc + col;
                if (FROM_OUT) v = fmaxf(g_out[(size_t)node * HID + j] + prevBias[j], 0.f);
                else          v = inp[(size_t)node * IN + j];
            }
            uint hb, lb; tf32_split(v, hb, lb);
            XsH[row][col] = hb; XsL[row][col] = lb;
        }
        for (int idx = t; idx < KC * 128; idx += 256) {
            int row = idx >> 7, col = idx & 127;
            int k = kc + row;
            float v = (col < HID) ? Wl[k * HID + col] : Wr[k * HID + (col - HID)];
            uint hb, lb; tf32_split(v, hb, lb);
            WsH[row][col] = hb; WsL[row][col] = lb;
        }
        __syncthreads();
        #pragma unroll
        for (int kk = 0; kk < KC; kk += 8) {
            uint aH[4], aL[4];
            aH[0] = XsH[mt * 16 + g    ][kk + c];
            aH[1] = XsH[mt * 16 + g + 8][kk + c];
            aH[2] = XsH[mt * 16 + g    ][kk + c + 4];
            aH[3] = XsH[mt * 16 + g + 8][kk + c + 4];
            aL[0] = XsL[mt * 16 + g    ][kk + c];
            aL[1] = XsL[mt * 16 + g + 8][kk + c];
            aL[2] = XsL[mt * 16 + g    ][kk + c + 4];
            aL[3] = XsL[mt * 16 + g + 8][kk + c + 4];
            #pragma unroll
            for (int nt = 0; nt < 8; ++nt) {
                int col = half * 64 + nt * 8 + g;
                uint bH0 = WsH[kk + c    ][col];
                uint bH1 = WsH[kk + c + 4][col];
                uint bL0 = WsL[kk + c    ][col];
                uint bL1 = WsL[kk + c + 4][col];
                mma_tf32(acc[nt], aH, bH0, bH1);
                mma_tf32(acc[nt], aL, bH0, bH1);
                mma_tf32(acc[nt], aH, bL0, bL1);
            }
        }
    }

    const float* bias = half ? br : bl;
    uint* dsth = reinterpret_cast<uint*>(half ? g_xrh : g_xlh);
    const int m0 = nb + mt * 16 + g;
    const int m1 = m0 + 8;
    #pragma unroll
    for (int nt = 0; nt < 8; ++nt) {
        int colL = nt * 8 + 2 * c;
        float bx = bias[colL], by = bias[colL + 1];
        if (m0 < N) {
            __half2 h = __floats2half2_rn(acc[nt][0] + bx, acc[nt][1] + by);
            dsth[(size_t)m0 * 32 + nt * 4 + c] = *reinterpret_cast<uint*>(&h);
        }
        if (m1 < N) {
            __half2 h = __floats2half2_rn(acc[nt][2] + bx, acc[nt][3] + by);
            dsth[(size_t)m1 * 32 + nt * 4 + c] = *reinterpret_cast<uint*>(&h);
        }
    }
}

// ---------------- edge pass A: fp16 tensor-core e-GEMM + logits (CSR order) --
__global__ __launch_bounds__(256) void edgeA_kernel(
        const float* __restrict__ We, const float* __restrict__ att,
        int Etot) {
    const int t = threadIdx.x;
    const int lane = t & 31;
    const int w = t >> 5;
    const int g = lane >> 2;                 // row group 0..7
    const int c = lane & 3;                  // col-in-group 0..3
    const int nTiles = (Etot + 15) >> 4;
    const int gw = blockIdx.x * 8 + w;
    const int gws = gridDim.x * 8;

    // preload B fragments (We as fp16) and att pairs into registers
    uint breg[8][2][2];
    float2 areg[8];
    #pragma unroll
    for (int nt = 0; nt < 8; ++nt) {
        const int n = nt * 8 + g;
        #pragma unroll
        for (int ks = 0; ks < 2; ++ks) {
            int k0 = ks * 16 + 2 * c;
            __half2 lo = __floats2half2_rn(We[k0 * HID + n],       We[(k0 + 1) * HID + n]);
            __half2 hi = __floats2half2_rn(We[(k0 + 8) * HID + n], We[(k0 + 9) * HID + n]);
            breg[nt][ks][0] = *reinterpret_cast<uint*>(&lo);
            breg[nt][ks][1] = *reinterpret_cast<uint*>(&hi);
        }
        areg[nt] = reinterpret_cast<const float2*>(att)[nt * 4 + c];
    }

    const uint* xlh = reinterpret_cast<const uint*>(g_xlh);
    const uint* xrh = reinterpret_cast<const uint*>(g_xrh);

    for (int tile = gw; tile < nTiles; tile += gws) {
        const int i0 = tile << 4;
        const int rowA = i0 + g;             // CSR slot
        const int rowB = i0 + g + 8;

        const int sA = g_csr_src[rowA], dA = g_csr_dst[rowA];
        const int sB = g_csr_src[rowB], dB = g_csr_dst[rowB];
        const uint* pA = reinterpret_cast<const uint*>(g_eap + (size_t)rowA * FE);
        const uint* pB = reinterpret_cast<const uint*>(g_eap + (size_t)rowB * FE);

        uint afr[2][4];
        #pragma unroll
        for (int ks = 0; ks < 2; ++ks) {
            afr[ks][0] = pA[ks * 8 + c];
            afr[ks][1] = pB[ks * 8 + c];
            afr[ks][2] = pA[ks * 8 + c + 4];
            afr[ks][3] = pB[ks * 8 + c + 4];
        }

        float partA = 0.f, partB = 0.f;
        #pragma unroll
        for (int nt = 0; nt < 8; ++nt) {
            float acc[4] = {0.f, 0.f, 0.f, 0.f};
            mma_f16(acc, afr[0][0], afr[0][1], afr[0][2], afr[0][3],
                    breg[nt][0][0], breg[nt][0][1]);
            mma_f16(acc, afr[1][0], afr[1][1], afr[1][2], afr[1][3],
                    breg[nt][1][0], breg[nt][1][1]);
            float2 xlA = h2f2(xlh[(size_t)sA * 32 + nt * 4 + c]);
            float2 xrA = h2f2(xrh[(size_t)dA * 32 + nt * 4 + c]);
            float2 xlB = h2f2(xlh[(size_t)sB * 32 + nt * 4 + c]);
            float2 xrB = h2f2(xrh[(size_t)dB * 32 + nt * 4 + c]);
            float u0 = acc[0] + xlA.x + xrA.x;
            float u1 = acc[1] + xlA.y + xrA.y;
            float u2 = acc[2] + xlB.x + xrB.x;
            float u3 = acc[3] + xlB.y + xrB.y;
            u0 = fmaxf(u0, 0.f) + 0.2f * fminf(u0, 0.f);
            u1 = fmaxf(u1, 0.f) + 0.2f * fminf(u1, 0.f);
            u2 = fmaxf(u2, 0.f) + 0.2f * fminf(u2, 0.f);
            u3 = fmaxf(u3, 0.f) + 0.2f * fminf(u3, 0.f);
            partA = fmaf(u0, areg[nt].x, fmaf(u1, areg[nt].y, partA));
            partB = fmaf(u2, areg[nt].x, fmaf(u3, areg[nt].y, partB));
        }
        partA += __shfl_xor_sync(0xffffffffu, partA, 1);
        partA += __shfl_xor_sync(0xffffffffu, partA, 2);
        partB += __shfl_xor_sync(0xffffffffu, partB, 1);
        partB += __shfl_xor_sync(0xffffffffu, partB, 2);
        if (c == 0) {
            if (rowA < Etot) g_exc[rowA] = __expf(partA);
            if (rowB < Etot) g_exc[rowB] = __expf(partB);
        }
    }
}

// ---------------- edge pass B: per-dst softmax-normalize + aggregate ---------
__global__ __launch_bounds__(256) void edgeB_kernel(int N) {
    const int lane = threadIdx.x & 31;
    const int d = blockIdx.x * 8 + (threadIdx.x >> 5);
    if (d >= N) return;
    const int rp0 = g_rowptr[d], rp1 = g_rowptr[d + 1];

    float den = 0.f;
    for (int e = rp0 + lane; e < rp1; e += 32) den += g_exc[e];
    #pragma unroll
    for (int off = 16; off > 0; off >>= 1)
        den += __shfl_xor_sync(0xffffffffu, den, off);
    const float inv = 1.f / den;

    const uint* xlh = reinterpret_cast<const uint*>(g_xlh);
    float ax = 0.f, ay = 0.f;
    int e = rp0;
    for (; e + 4 <= rp1; e += 4) {
        int s0 = g_csr_src[e],     s1 = g_csr_src[e + 1];
        int s2 = g_csr_src[e + 2], s3 = g_csr_src[e + 3];
        float w0 = g_exc[e],     w1 = g_exc[e + 1];
        float w2 = g_exc[e + 2], w3 = g_exc[e + 3];
        float2 v0 = h2f2(xlh[(size_t)s0 * 32 + lane]);
        float2 v1 = h2f2(xlh[(size_t)s1 * 32 + lane]);
        float2 v2 = h2f2(xlh[(size_t)s2 * 32 + lane]);
        float2 v3 = h2f2(xlh[(size_t)s3 * 32 + lane]);
        ax = fmaf(w0, v0.x, fmaf(w1, v1.x, fmaf(w2, v2.x, fmaf(w3, v3.x, ax))));
        ay = fmaf(w0, v0.y, fmaf(w1, v1.y, fmaf(w2, v2.y, fmaf(w3, v3.y, ay))));
    }
    for (; e < rp1; ++e) {
        int s = g_csr_src[e];
        float wgt = g_exc[e];
        float2 xv = h2f2(xlh[(size_t)s * 32 + lane]);
        ax = fmaf(wgt, xv.x, ax);
        ay = fmaf(wgt, xv.y, ay);
    }
    float2* out2 = reinterpret_cast<float2*>(g_out);
    out2[(size_t)d * 32 + lane] = make_float2(ax * inv, ay * inv);
}

// ---------------- kernel: final MLP at node_idx (+ restore g_deg = 0) --------
__global__ void fin_kernel(const int* __restrict__ idx, const float* __restrict__ bias2,
                           const float* __restrict__ y,
                           const float* __restrict__ W0, const float* __restrict__ b0,
                           const float* __restrict__ W1, const float* __restrict__ b1,
                           const float* __restrict__ W2, const float* __restrict__ b2,
                           float* __restrict__ dout, int M, int rf, int N) {
    // restore the g_deg == 0 invariant for the next launch
    for (int z = blockIdx.x * blockDim.x + threadIdx.x; z < N; z += gridDim.x * blockDim.x)
        g_deg[z] = 0;

    __shared__ float sh[4][64];
    __shared__ float sz[4][32];
    const int w = threadIdx.x >> 5, lane = threadIdx.x & 31;
    const int m = blockIdx.x * 4 + w;
    if (m >= M) return;
    const int v = idx[m];

    float h0 = fmaxf(g_out[(size_t)v * HID + lane]      + bias2[lane],      0.f);
    float h1 = fmaxf(g_out[(size_t)v * HID + 32 + lane] + bias2[32 + lane], 0.f);
    sh[w][lane] = h0; sh[w][32 + lane] = h1;
    __syncwarp();

    int k = v / rf;
    float y0 = y[2 * k], y1 = y[2 * k + 1];
    float q0 = fmaxf(y0 * W0[0] + y1 * W0[2] + b0[0], 0.f);
    float q1 = fmaxf(y0 * W0[1] + y1 * W0[3] + b0[1], 0.f);

    float z = b1[lane];
    #pragma unroll
    for (int j = 0; j < 64; ++j) z += sh[w][j] * W1[j * 32 + lane];
    z += q0 * W1[64 * 32 + lane] + q1 * W1[65 * 32 + lane];
    z = fmaxf(z, 0.f);
    sz[w][lane] = z;
    __syncwarp();

    float o = b2[lane];
    #pragma unroll
    for (int j = 0; j < 32; ++j) o += sz[w][j] * W2[j * 32 + lane];
    dout[m * 32 + lane] = o;
}

// ---------------- launch ------------------------------------------------------
extern "C" void kernel_launch(void* const* d_in, const int* in_sizes, int n_in,
                              void* d_out, int out_size) {
    const float* x    = (const float*)d_in[0];
    const float* ea   = (const float*)d_in[1];
    const float* y    = (const float*)d_in[2];
    const float* Wl1  = (const float*)d_in[3];
    const float* bl1  = (const float*)d_in[4];
    const float* Wr1  = (const float*)d_in[5];
    const float* br1  = (const float*)d_in[6];
    const float* We1  = (const float*)d_in[7];
    const float* att1 = (const float*)d_in[8];
    const float* bias1= (const float*)d_in[9];
    const float* Wl2  = (const float*)d_in[10];
    const float* bl2  = (const float*)d_in[11];
    const float* Wr2  = (const float*)d_in[12];
    const float* br2  = (const float*)d_in[13];
    const float* We2  = (const float*)d_in[14];
    const float* att2 = (const float*)d_in[15];
    const float* bias2= (const float*)d_in[16];
    const float* W0   = (const float*)d_in[17];
    const float* b0   = (const float*)d_in[18];
    const float* W1   = (const float*)d_in[19];
    const float* b1   = (const float*)d_in[20];
    const float* W2   = (const float*)d_in[21];
    const float* b2   = (const float*)d_in[22];
    const int*   ei   = (const int*)  d_in[23];
    const int*   nidx = (const int*)  d_in[24];

    const int N    = in_sizes[0] / FN;
    const int E    = in_sizes[23] / 2;
    const int Etot = E + N;
    const int M    = in_sizes[24];
    const int NG   = in_sizes[2] / 2;
    const int rf   = N / NG;

    const int EBLK = (E + 255) / 256;
    const int NWRP = (N + 7) / 8;        // warp-per-node kernels
    const int NB1K = (N + 1023) / 1024;  // 1024-thread node kernels

    // ---- CSR build + permuted fp16 edge attrs + self-loop mean ----
    deg_kernel     <<<EBLK, 256>>>(ei, E);
    scanA_kernel   <<<NB1K, 1024>>>(N);
    scanB_kernel   <<<1, 128>>>(NB1K);
    scanC_kernel   <<<NB1K, 1024>>>(N, Etot);
    scatter_kernel <<<EBLK, 256>>>(ei, ea, E);
    pre_csr_kernel <<<NWRP, 256>>>(N);

    // ---- layer 1 ----
    lin_mma_kernel<FN, false><<<(N + 63) / 64, 256>>>(x, Wl1, bl1, Wr1, br1, nullptr, N);
    edgeA_kernel<<<2048, 256>>>(We1, att1, Etot);
    edgeB_kernel<<<NWRP, 256>>>(N);

    // ---- layer 2 ----
    lin_mma_kernel<HID, true><<<(N + 63) / 64, 256>>>(x, Wl2, bl2, Wr2, br2, bias1, N);
    edgeA_kernel<<<2048, 256>>>(We2, att2, Etot);
    edgeB_kernel<<<NWRP, 256>>>(N);

    // ---- final MLP at node_idx (also restores g_deg = 0) ----
    fin_kernel<<<(M + 3) / 4, 128>>>(nidx, bias2, y, W0, b0, W1, b1, W2, b2,
                                     (float*)d_out, M, rf, N);
}

// round 10
// speedup vs baseline: 3.1294x; 2.2278x over previous
#include <cuda_runtime.h>
#include <cuda_fp16.h>
#include <cstddef>

typedef unsigned long long ull;
typedef unsigned int uint;

// ---------------- problem constants (shapes fixed by the dataset) -----------
#define MAXN 100000
#define MAXE 1600000
#define MAXET (MAXE + MAXN)
#define MAXETP (MAXET + 16)   // padded (edgeA tile overrun reads zero row)
#define FN   128     // node feature dim (layer1 input)
#define FE   32      // edge feature dim
#define HID  64

// ---------------- device scratch (static: no allocation allowed) ------------
__device__ __align__(16) __half g_xlh[MAXN * HID];  // source-side transform (fp16)
__device__ __align__(16) __half g_xrh[MAXN * HID];  // target-side transform (fp16)
__device__ float  g_exc [MAXETP];           // exp(logit), CSR slot order
__device__ float  g_out [MAXN * HID];       // layer output (valid at T1 nodes)
__device__ int    g_deg [MAXN];             // zero at entry (restored by fin)
__device__ int    g_mark1[MAXN];            // zero at entry (restored by fin)
__device__ int    g_mark2[MAXN];            // zero at entry (restored by fin)
__device__ int    g_rowptr[MAXN + 1];
__device__ int    g_cur [MAXN];
__device__ int    g_bsum[128];
__device__ int    g_csr_src[MAXETP];        // src per CSR slot (T1 segments only)
__device__ int    g_csr_dst[MAXETP];        // dst per CSR slot (T1 segments only)
__device__ int    g_list1[MAXN];            // compacted T1 node list
__device__ int    g_list2[MAXN];            // compacted T2 node list
__device__ int    g_asl1[MAXETP];           // active CSR slots, layer 1
__device__ int    g_asl2[MAXETP];           // active CSR slots, layer 2
__device__ int    g_n1, g_n2, g_nasl1, g_nasl2;   // zero at entry (fin restores)
__device__ __align__(16) __half g_eap[(size_t)MAXETP * FE];  // permuted fp16 edge attrs

// ---------------- small helpers ---------------------------------------------
__device__ __forceinline__ void tf32_split(float v, uint& hb, uint& lb) {
    asm("cvt.rna.tf32.f32 %0, %1;" : "=r"(hb) : "f"(v));
    float hf = __uint_as_float(hb);
    asm("cvt.rna.tf32.f32 %0, %1;" : "=r"(lb) : "f"(v - hf));
}
__device__ __forceinline__ void mma_tf32(float acc[4], const uint a[4], uint b0, uint b1) {
    asm volatile(
        "mma.sync.aligned.m16n8k8.row.col.f32.tf32.tf32.f32 "
        "{%0,%1,%2,%3}, {%4,%5,%6,%7}, {%8,%9}, {%0,%1,%2,%3};"
        : "+f"(acc[0]), "+f"(acc[1]), "+f"(acc[2]), "+f"(acc[3])
        : "r"(a[0]), "r"(a[1]), "r"(a[2]), "r"(a[3]), "r"(b0), "r"(b1));
}
__device__ __forceinline__ void mma_f16(float acc[4], uint a0, uint a1, uint a2, uint a3,
                                        uint b0, uint b1) {
    asm volatile(
        "mma.sync.aligned.m16n8k16.row.col.f32.f16.f16.f32 "
        "{%0,%1,%2,%3}, {%4,%5,%6,%7}, {%8,%9}, {%0,%1,%2,%3};"
        : "+f"(acc[0]), "+f"(acc[1]), "+f"(acc[2]), "+f"(acc[3])
        : "r"(a0), "r"(a1), "r"(a2), "r"(a3), "r"(b0), "r"(b1));
}
__device__ __forceinline__ float2 h2f2(uint v) {
    __half2 h = *reinterpret_cast<__half2*>(&v);
    return __half22float2(h);
}

// ================= active-set construction ===================================
// T2 = distinct(node_idx); every T2 node also enters T1.
__global__ void mark2_kernel(const int* __restrict__ nidx, int M) {
    int m = blockIdx.x * blockDim.x + threadIdx.x;
    if (m >= M) return;
    int d = nidx[m];
    if (atomicExch(&g_mark2[d], 1) == 0) { int p = atomicAdd(&g_n2, 1); g_list2[p] = d; }
    if (atomicExch(&g_mark1[d], 1) == 0) { int p = atomicAdd(&g_n1, 1); g_list1[p] = d; }
}

// T1 += sources of edges whose dst is in T2 (original edge list, no CSR needed)
__global__ void markS_kernel(const int* __restrict__ ei, int E) {
    int i = blockIdx.x * blockDim.x + threadIdx.x;
    if (i >= E) return;
    int d = ei[E + i];
    if (g_mark2[d]) {
        int s = ei[i];
        if (atomicExch(&g_mark1[s], 1) == 0) { int p = atomicAdd(&g_n1, 1); g_list1[p] = s; }
    }
}

// ================= CSR build ==================================================
__global__ void deg_kernel(const int* __restrict__ ei, int E) {
    int i = blockIdx.x * blockDim.x + threadIdx.x;
    if (i >= E) return;
    atomicAdd(&g_deg[ei[E + i]], 1);
}

// grid scan stage A: per-block exclusive scan + block sums (deg+1: self loop)
__global__ __launch_bounds__(1024) void scanA_kernel(int N) {
    __shared__ int wsum[32];
    const int i = blockIdx.x * 1024 + threadIdx.x;
    const int lane = threadIdx.x & 31, wid = threadIdx.x >> 5;
    int v = (i < N) ? (g_deg[i] + 1) : 0;
    int s = v;
    #pragma unroll
    for (int off = 1; off < 32; off <<= 1) {
        int t = __shfl_up_sync(0xffffffffu, s, off);
        if (lane >= off) s += t;
    }
    if (lane == 31) wsum[wid] = s;
    __syncthreads();
    if (wid == 0) {
        int ws = wsum[lane];
        #pragma unroll
        for (int off = 1; off < 32; off <<= 1) {
            int t = __shfl_up_sync(0xffffffffu, ws, off);
            if (lane >= off) ws += t;
        }
        wsum[lane] = ws;
    }
    __syncthreads();
    int excl = s - v + (wid ? wsum[wid - 1] : 0);
    if (i < N) g_rowptr[i] = excl;
    if (threadIdx.x == 1023) g_bsum[blockIdx.x] = excl + v;
}

__global__ void scanB_kernel(int nb) {
    __shared__ int sh[128];
    const int t = threadIdx.x;
    int v = (t < nb) ? g_bsum[t] : 0;
    sh[t] = v;
    __syncthreads();
    for (int off = 1; off < 128; off <<= 1) {
        int x = (t >= off) ? sh[t - off] : 0;
        __syncthreads();
        sh[t] += x;
        __syncthreads();
    }
    g_bsum[t] = sh[t] - v;
}

__global__ __launch_bounds__(1024) void scanC_kernel(int N, int Etot) {
    int i = blockIdx.x * 1024 + threadIdx.x;
    if (i < N) {
        int rp = g_rowptr[i] + g_bsum[blockIdx.x];
        g_rowptr[i] = rp;
        g_cur[i]    = rp;
    }
    if (i == 0) g_rowptr[N] = Etot;
}

// scatter + permute + fp16-convert edge attrs, FILTERED to T1 destinations.
__global__ void scatter_kernel(const int* __restrict__ ei, const float* __restrict__ ea, int E) {
    int i = blockIdx.x * blockDim.x + threadIdx.x;
    if (i >= E) return;
    int d = ei[E + i];
    if (!g_mark1[d]) return;
    int s = ei[i];
    int pos = atomicAdd(&g_cur[d], 1);
    g_csr_src[pos] = s;
    g_csr_dst[pos] = d;
    const float4* r4 = reinterpret_cast<const float4*>(ea) + (size_t)i * 8;
    __half2* dst = reinterpret_cast<__half2*>(g_eap + (size_t)pos * FE);
    #pragma unroll
    for (int q = 0; q < 8; ++q) {
        float4 v = r4[q];
        dst[2 * q]     = __floats2half2_rn(v.x, v.y);
        dst[2 * q + 1] = __floats2half2_rn(v.z, v.w);
    }
}

// append all CSR slots of listed nodes to the active-slot list
__global__ void build_kernel(int layer) {
    const int* list = (layer == 1) ? g_list1 : g_list2;
    const int  n    = (layer == 1) ? g_n1    : g_n2;
    int*       asl  = (layer == 1) ? g_asl1  : g_asl2;
    int*       pn   = (layer == 1) ? &g_nasl1 : &g_nasl2;
    const int lane = threadIdx.x & 31;
    const int gws = gridDim.x * 8;
    for (int widx = blockIdx.x * 8 + (threadIdx.x >> 5); widx < n; widx += gws) {
        int d = list[widx];
        int rp0 = g_rowptr[d], len = g_rowptr[d + 1] - rp0;
        int base;
        if (lane == 0) base = atomicAdd(pn, len);
        base = __shfl_sync(0xffffffffu, base, 0);
        for (int k = lane; k < len; k += 32) asl[base + k] = rp0 + k;
    }
}

// ---------------- self-loop attr: per-T1-segment mean ------------------------
__global__ void pre_csr_kernel() {
    const int lane = threadIdx.x & 31;
    const int gws = gridDim.x * 8;
    const int n1 = g_n1;
    for (int widx = blockIdx.x * 8 + (threadIdx.x >> 5); widx < n1; widx += gws) {
        const int d = g_list1[widx];
        const int rp0 = g_rowptr[d], rp1 = g_rowptr[d + 1];
        const int last = rp1 - 1;            // self-loop slot
        float s = 0.f;
        int e = rp0;
        for (; e + 4 <= last; e += 4) {
            float a0 = __half2float(g_eap[(size_t)(e + 0) * FE + lane]);
            float a1 = __half2float(g_eap[(size_t)(e + 1) * FE + lane]);
            float a2 = __half2float(g_eap[(size_t)(e + 2) * FE + lane]);
            float a3 = __half2float(g_eap[(size_t)(e + 3) * FE + lane]);
            s += (a0 + a1) + (a2 + a3);
        }
        for (; e < last; ++e) s += __half2float(g_eap[(size_t)e * FE + lane]);
        float mean = s / (float)max(last - rp0, 1);
        g_eap[(size_t)last * FE + lane] = __float2half_rn(mean);
        if (lane == 0) { g_csr_src[last] = d; g_csr_dst[last] = d; }
    }
}

// ---------------- node linear transforms via 3xTF32 tensor MMA ---------------
// LIST mode (layer 2): block handles 64 entries of g_list1; reads g_out.
template<int IN, bool LIST>
__global__ __launch_bounds__(256) void lin_mma_kernel(
        const float* __restrict__ inp,
        const float* __restrict__ Wl, const float* __restrict__ bl,
        const float* __restrict__ Wr, const float* __restrict__ br,
        const float* __restrict__ prevBias, int N) {
    const int nb = blockIdx.x * 64;
    const int nlim = LIST ? g_n1 : N;
    if (nb >= nlim) return;

    constexpr int KC = 16;
    __shared__ uint XsH[64][20], XsL[64][20];
    __shared__ uint WsH[KC][132], WsL[KC][132];

    const int t = threadIdx.x;
    const int lane = t & 31;
    const int w = t >> 5;
    const int mt = w & 3;
    const int half = w >> 2;
    const int g = lane >> 2, c = lane & 3;

    float acc[8][4];
    #pragma unroll
    for (int nt = 0; nt < 8; ++nt) {
        acc[nt][0] = acc[nt][1] = acc[nt][2] = acc[nt][3] = 0.f;
    }

    for (int kc = 0; kc < IN; kc += KC) {
        __syncthreads();
        for (int idx = t; idx < 64 * KC; idx += 256) {
            int row = idx / KC, col = idx - row * KC;
            int m = nb + row;
            float v = 0.f;
            if (m < nlim) {
                int node = LIST ? g_list1[m] : m;
                int j = kc + col;
                if (LIST) v = fmaxf(g_out[(size_t)node * HID + j] + prevBias[j], 0.f);
                else      v = inp[(size_t)node * IN + j];
            }
            uint hb, lb; tf32_split(v, hb, lb);
            XsH[row][col] = hb; XsL[row][col] = lb;
        }
        for (int idx = t; idx < KC * 128; idx += 256) {
            int row = idx >> 7, col = idx & 127;
            int k = kc + row;
            float v = (col < HID) ? Wl[k * HID + col] : Wr[k * HID + (col - HID)];
            uint hb, lb; tf32_split(v, hb, lb);
            WsH[row][col] = hb; WsL[row][col] = lb;
        }
        __syncthreads();
        #pragma unroll
        for (int kk = 0; kk < KC; kk += 8) {
            uint aH[4], aL[4];
            aH[0] = XsH[mt * 16 + g    ][kk + c];
            aH[1] = XsH[mt * 16 + g + 8][kk + c];
            aH[2] = XsH[mt * 16 + g    ][kk + c + 4];
            aH[3] = XsH[mt * 16 + g + 8][kk + c + 4];
            aL[0] = XsL[mt * 16 + g    ][kk + c];
            aL[1] = XsL[mt * 16 + g + 8][kk + c];
            aL[2] = XsL[mt * 16 + g    ][kk + c + 4];
            aL[3] = XsL[mt * 16 + g + 8][kk + c + 4];
            #pragma unroll
            for (int nt = 0; nt < 8; ++nt) {
                int col = half * 64 + nt * 8 + g;
                uint bH0 = WsH[kk + c    ][col];
                uint bH1 = WsH[kk + c + 4][col];
                uint bL0 = WsL[kk + c    ][col];
                uint bL1 = WsL[kk + c + 4][col];
                mma_tf32(acc[nt], aH, bH0, bH1);
                mma_tf32(acc[nt], aL, bH0, bH1);
                mma_tf32(acc[nt], aH, bL0, bL1);
            }
        }
    }

    const float* bias = half ? br : bl;
    uint* dsth = reinterpret_cast<uint*>(half ? g_xrh : g_xlh);
    const int m0 = nb + mt * 16 + g;
    const int m1 = m0 + 8;
    const int node0 = (m0 < nlim) ? (LIST ? g_list1[m0] : m0) : -1;
    const int node1 = (m1 < nlim) ? (LIST ? g_list1[m1] : m1) : -1;
    #pragma unroll
    for (int nt = 0; nt < 8; ++nt) {
        int colL = nt * 8 + 2 * c;
        float bx = bias[colL], by = bias[colL + 1];
        if (node0 >= 0) {
            __half2 h = __floats2half2_rn(acc[nt][0] + bx, acc[nt][1] + by);
            dsth[(size_t)node0 * 32 + nt * 4 + c] = *reinterpret_cast<uint*>(&h);
        }
        if (node1 >= 0) {
            __half2 h = __floats2half2_rn(acc[nt][2] + bx, acc[nt][3] + by);
            dsth[(size_t)node1 * 32 + nt * 4 + c] = *reinterpret_cast<uint*>(&h);
        }
    }
}

// ---------------- edge pass A: fp16 MMA e-GEMM + logits over active slots ----
__global__ __launch_bounds__(256) void edgeA_kernel(
        const float* __restrict__ We, const float* __restrict__ att, int layer) {
    const int* __restrict__ asl = (layer == 1) ? g_asl1 : g_asl2;
    const int nasl = (layer == 1) ? g_nasl1 : g_nasl2;

    const int t = threadIdx.x;
    const int lane = t & 31;
    const int w = t >> 5;
    const int g = lane >> 2;                 // row group 0..7
    const int c = lane & 3;                  // col-in-group 0..3
    const int nTiles = (nasl + 15) >> 4;
    const int gw = blockIdx.x * 8 + w;
    const int gws = gridDim.x * 8;

    // preload B fragments (We as fp16) and att pairs into registers
    uint breg[8][2][2];
    float2 areg[8];
    #pragma unroll
    for (int nt = 0; nt < 8; ++nt) {
        const int n = nt * 8 + g;
        #pragma unroll
        for (int ks = 0; ks < 2; ++ks) {
            int k0 = ks * 16 + 2 * c;
            __half2 lo = __floats2half2_rn(We[k0 * HID + n],       We[(k0 + 1) * HID + n]);
            __half2 hi = __floats2half2_rn(We[(k0 + 8) * HID + n], We[(k0 + 9) * HID + n]);
            breg[nt][ks][0] = *reinterpret_cast<uint*>(&lo);
            breg[nt][ks][1] = *reinterpret_cast<uint*>(&hi);
        }
        areg[nt] = reinterpret_cast<const float2*>(att)[nt * 4 + c];
    }

    const uint* xlh = reinterpret_cast<const uint*>(g_xlh);
    const uint* xrh = reinterpret_cast<const uint*>(g_xrh);

    for (int tile = gw; tile < nTiles; tile += gws) {
        const int iA = tile * 16 + g;
        const int iB = iA + 8;
        const int rowA = (iA < nasl) ? asl[iA] : MAXET;   // pad row: zeros
        const int rowB = (iB < nasl) ? asl[iB] : MAXET;

        const int sA = g_csr_src[rowA], dA = g_csr_dst[rowA];
        const int sB = g_csr_src[rowB], dB = g_csr_dst[rowB];
        const uint* pA = reinterpret_cast<const uint*>(g_eap + (size_t)rowA * FE);
        const uint* pB = reinterpret_cast<const uint*>(g_eap + (size_t)rowB * FE);

        uint afr[2][4];
        #pragma unroll
        for (int ks = 0; ks < 2; ++ks) {
            afr[ks][0] = pA[ks * 8 + c];
            afr[ks][1] = pB[ks * 8 + c];
            afr[ks][2] = pA[ks * 8 + c + 4];
            afr[ks][3] = pB[ks * 8 + c + 4];
        }

        float partA = 0.f, partB = 0.f;
        #pragma unroll
        for (int nt = 0; nt < 8; ++nt) {
            float acc[4] = {0.f, 0.f, 0.f, 0.f};
            mma_f16(acc, afr[0][0], afr[0][1], afr[0][2], afr[0][3],
                    breg[nt][0][0], breg[nt][0][1]);
            mma_f16(acc, afr[1][0], afr[1][1], afr[1][2], afr[1][3],
                    breg[nt][1][0], breg[nt][1][1]);
            float2 xlA = h2f2(xlh[(size_t)sA * 32 + nt * 4 + c]);
            float2 xrA = h2f2(xrh[(size_t)dA * 32 + nt * 4 + c]);
            float2 xlB = h2f2(xlh[(size_t)sB * 32 + nt * 4 + c]);
            float2 xrB = h2f2(xrh[(size_t)dB * 32 + nt * 4 + c]);
            float u0 = acc[0] + xlA.x + xrA.x;
            float u1 = acc[1] + xlA.y + xrA.y;
            float u2 = acc[2] + xlB.x + xrB.x;
            float u3 = acc[3] + xlB.y + xrB.y;
            u0 = fmaxf(u0, 0.f) + 0.2f * fminf(u0, 0.f);
            u1 = fmaxf(u1, 0.f) + 0.2f * fminf(u1, 0.f);
            u2 = fmaxf(u2, 0.f) + 0.2f * fminf(u2, 0.f);
            u3 = fmaxf(u3, 0.f) + 0.2f * fminf(u3, 0.f);
            partA = fmaf(u0, areg[nt].x, fmaf(u1, areg[nt].y, partA));
            partB = fmaf(u2, areg[nt].x, fmaf(u3, areg[nt].y, partB));
        }
        partA += __shfl_xor_sync(0xffffffffu, partA, 1);
        partA += __shfl_xor_sync(0xffffffffu, partA, 2);
        partB += __shfl_xor_sync(0xffffffffu, partB, 1);
        partB += __shfl_xor_sync(0xffffffffu, partB, 2);
        if (c == 0) {
            if (iA < nasl) g_exc[rowA] = __expf(partA);
            if (iB < nasl) g_exc[rowB] = __expf(partB);
        }
    }
}

// ---------------- edge pass B: softmax-normalize + aggregate (listed nodes) --
__global__ __launch_bounds__(256) void edgeB_kernel(int layer) {
    const int* list = (layer == 1) ? g_list1 : g_list2;
    const int  n    = (layer == 1) ? g_n1    : g_n2;
    const int lane = threadIdx.x & 31;
    const int gws = gridDim.x * 8;
    const uint* xlh = reinterpret_cast<const uint*>(g_xlh);

    for (int widx = blockIdx.x * 8 + (threadIdx.x >> 5); widx < n; widx += gws) {
        const int d = list[widx];
        const int rp0 = g_rowptr[d], rp1 = g_rowptr[d + 1];

        float den = 0.f;
        for (int e = rp0 + lane; e < rp1; e += 32) den += g_exc[e];
        #pragma unroll
        for (int off = 16; off > 0; off >>= 1)
            den += __shfl_xor_sync(0xffffffffu, den, off);
        const float inv = 1.f / den;

        float ax = 0.f, ay = 0.f;
        int e = rp0;
        for (; e + 4 <= rp1; e += 4) {
            int s0 = g_csr_src[e],     s1 = g_csr_src[e + 1];
            int s2 = g_csr_src[e + 2], s3 = g_csr_src[e + 3];
            float w0 = g_exc[e],     w1 = g_exc[e + 1];
            float w2 = g_exc[e + 2], w3 = g_exc[e + 3];
            float2 v0 = h2f2(xlh[(size_t)s0 * 32 + lane]);
            float2 v1 = h2f2(xlh[(size_t)s1 * 32 + lane]);
            float2 v2 = h2f2(xlh[(size_t)s2 * 32 + lane]);
            float2 v3 = h2f2(xlh[(size_t)s3 * 32 + lane]);
            ax = fmaf(w0, v0.x, fmaf(w1, v1.x, fmaf(w2, v2.x, fmaf(w3, v3.x, ax))));
            ay = fmaf(w0, v0.y, fmaf(w1, v1.y, fmaf(w2, v2.y, fmaf(w3, v3.y, ay))));
        }
        for (; e < rp1; ++e) {
            int s = g_csr_src[e];
            float wgt = g_exc[e];
            float2 xv = h2f2(xlh[(size_t)s * 32 + lane]);
            ax = fmaf(wgt, xv.x, ax);
            ay = fmaf(wgt, xv.y, ay);
        }
        float2* out2 = reinterpret_cast<float2*>(g_out);
        out2[(size_t)d * 32 + lane] = make_float2(ax * inv, ay * inv);
    }
}

// ---------------- final MLP at node_idx + restore zero-invariants ------------
__global__ void fin_kernel(const int* __restrict__ idx, const float* __restrict__ bias2,
                           const float* __restrict__ y,
                           const float* __restrict__ W0, const float* __restrict__ b0,
                           const float* __restrict__ W1, const float* __restrict__ b1,
                           const float* __restrict__ W2, const float* __restrict__ b2,
                           float* __restrict__ dout, int M, int rf, int N) {
    // restore zero-invariants for the next launch (graph replay safe)
    int tid = blockIdx.x * blockDim.x + threadIdx.x;
    for (int z = tid; z < N; z += gridDim.x * blockDim.x) {
        g_deg[z] = 0; g_mark1[z] = 0; g_mark2[z] = 0;
    }
    if (tid == 0) { g_n1 = 0; g_n2 = 0; g_nasl1 = 0; g_nasl2 = 0; }

    __shared__ float sh[4][64];
    __shared__ float sz[4][32];
    const int w = threadIdx.x >> 5, lane = threadIdx.x & 31;
    const int m = blockIdx.x * 4 + w;
    if (m >= M) return;
    const int v = idx[m];

    float h0 = fmaxf(g_out[(size_t)v * HID + lane]      + bias2[lane],      0.f);
    float h1 = fmaxf(g_out[(size_t)v * HID + 32 + lane] + bias2[32 + lane], 0.f);
    sh[w][lane] = h0; sh[w][32 + lane] = h1;
    __syncwarp();

    int k = v / rf;
    float y0 = y[2 * k], y1 = y[2 * k + 1];
    float q0 = fmaxf(y0 * W0[0] + y1 * W0[2] + b0[0], 0.f);
    float q1 = fmaxf(y0 * W0[1] + y1 * W0[3] + b0[1], 0.f);

    float z = b1[lane];
    #pragma unroll
    for (int j = 0; j < 64; ++j) z += sh[w][j] * W1[j * 32 + lane];
    z += q0 * W1[64 * 32 + lane] + q1 * W1[65 * 32 + lane];
    z = fmaxf(z, 0.f);
    sz[w][lane] = z;
    __syncwarp();

    float o = b2[lane];
    #pragma unroll
    for (int j = 0; j < 32; ++j) o += sz[w][j] * W2[j * 32 + lane];
    dout[m * 32 + lane] = o;
}

// ---------------- launch ------------------------------------------------------
extern "C" void kernel_launch(void* const* d_in, const int* in_sizes, int n_in,
                              void* d_out, int out_size) {
    const float* x    = (const float*)d_in[0];
    const float* ea   = (const float*)d_in[1];
    const float* y    = (const float*)d_in[2];
    const float* Wl1  = (const float*)d_in[3];
    const float* bl1  = (const float*)d_in[4];
    const float* Wr1  = (const float*)d_in[5];
    const float* br1  = (const float*)d_in[6];
    const float* We1  = (const float*)d_in[7];
    const float* att1 = (const float*)d_in[8];
    const float* bias1= (const float*)d_in[9];
    const float* Wl2  = (const float*)d_in[10];
    const float* bl2  = (const float*)d_in[11];
    const float* Wr2  = (const float*)d_in[12];
    const float* br2  = (const float*)d_in[13];
    const float* We2  = (const float*)d_in[14];
    const float* att2 = (const float*)d_in[15];
    const float* bias2= (const float*)d_in[16];
    const float* W0   = (const float*)d_in[17];
    const float* b0   = (const float*)d_in[18];
    const float* W1   = (const float*)d_in[19];
    const float* b1   = (const float*)d_in[20];
    const float* W2   = (const float*)d_in[21];
    const float* b2   = (const float*)d_in[22];
    const int*   ei   = (const int*)  d_in[23];
    const int*   nidx = (const int*)  d_in[24];

    const int N    = in_sizes[0] / FN;
    const int E    = in_sizes[23] / 2;
    const int Etot = E + N;
    const int M    = in_sizes[24];
    const int NG   = in_sizes[2] / 2;
    const int rf   = N / NG;

    const int EBLK = (E + 255) / 256;
    const int NB1K = (N + 1023) / 1024;

    // ---- active sets ----
    mark2_kernel   <<<(M + 255) / 256, 256>>>(nidx, M);
    markS_kernel   <<<EBLK, 256>>>(ei, E);

    // ---- CSR build (rowptr full; payload filtered to T1 segments) ----
    deg_kernel     <<<EBLK, 256>>>(ei, E);
    scanA_kernel   <<<NB1K, 1024>>>(N);
    scanB_kernel   <<<1, 128>>>(NB1K);
    scanC_kernel   <<<NB1K, 1024>>>(N, Etot);
    scatter_kernel <<<EBLK, 256>>>(ei, ea, E);
    build_kernel   <<<512, 256>>>(1);
    build_kernel   <<<128, 256>>>(2);
    pre_csr_kernel <<<512, 256>>>();

    // ---- layer 1 (lin over all nodes; edges over T1 segments) ----
    lin_mma_kernel<FN, false><<<(N + 63) / 64, 256>>>(x, Wl1, bl1, Wr1, br1, nullptr, N);
    edgeA_kernel<<<2048, 256>>>(We1, att1, 1);
    edgeB_kernel<<<1024, 256>>>(1);

    // ---- layer 2 (lin over T1 list; edges over T2 segments) ----
    lin_mma_kernel<HID, true><<<(N + 63) / 64, 256>>>(x, Wl2, bl2, Wr2, br2, bias1, N);
    edgeA_kernel<<<512, 256>>>(We2, att2, 2);
    edgeB_kernel<<<256, 256>>>(2);

    // ---- final MLP at node_idx (also restores zero-invariants) ----
    fin_kernel<<<512, 128>>>(nidx, bias2, y, W0, b0, W1, b1, W2, b2,
                             (float*)d_out, M, rf, N);
}

// round 11
// speedup vs baseline: 3.1930x; 1.0203x over previous
#include <cuda_runtime.h>
#include <cuda_fp16.h>
#include <cstddef>

typedef unsigned long long ull;
typedef unsigned int uint;

// ---------------- problem constants (shapes fixed by the dataset) -----------
#define MAXN 100000
#define MAXE 1600000
#define MAXET (MAXE + MAXN)
#define MAXETP (MAXET + 16)   // padded (edgeA tile overrun reads zero row)
#define FN   128     // node feature dim (layer1 input)
#define FE   32      // edge feature dim
#define HID  64

// ---------------- device scratch (static: no allocation allowed) ------------
__device__ __align__(16) __half g_xlh[MAXN * HID];  // source-side transform (fp16)
__device__ __align__(16) __half g_xrh[MAXN * HID];  // target-side transform (fp16)
__device__ float  g_exc [MAXETP];           // exp(logit), compact CSR slot order
__device__ float  g_out [MAXN * HID];       // layer output (valid at T1 nodes)
__device__ int    g_degc[MAXN];             // degree per T1 index (zero at entry)
__device__ int    g_mark1[MAXN];            // T1 index+1, 0 = inactive (zeroed by fin)
__device__ int    g_mark2[MAXN];            // T2 index+1, 0 = inactive (zeroed by fin)
__device__ int    g_rowptr[MAXN + 1];       // compact rowptr over T1 indices
__device__ int    g_cur [MAXN];
__device__ int    g_bsum[128];
__device__ int    g_csr_src[MAXETP];        // src node per compact slot
__device__ int    g_csr_dst[MAXETP];        // dst node per compact slot
__device__ int    g_list1[MAXN];            // compacted T1 node list
__device__ int    g_list2[MAXN];            // compacted T2 node list
__device__ int    g_asl2[MAXETP];           // active compact slots, layer 2
__device__ int    g_n1, g_n2, g_nasl1, g_nasl2;   // zero at entry (fin restores)
__device__ __align__(16) __half g_eap[(size_t)MAXETP * FE];  // permuted fp16 edge attrs

// ---------------- small helpers ---------------------------------------------
__device__ __forceinline__ void tf32_split(float v, uint& hb, uint& lb) {
    asm("cvt.rna.tf32.f32 %0, %1;" : "=r"(hb) : "f"(v));
    float hf = __uint_as_float(hb);
    asm("cvt.rna.tf32.f32 %0, %1;" : "=r"(lb) : "f"(v - hf));
}
__device__ __forceinline__ void mma_tf32(float acc[4], const uint a[4], uint b0, uint b1) {
    asm volatile(
        "mma.sync.aligned.m16n8k8.row.col.f32.tf32.tf32.f32 "
        "{%0,%1,%2,%3}, {%4,%5,%6,%7}, {%8,%9}, {%0,%1,%2,%3};"
        : "+f"(acc[0]), "+f"(acc[1]), "+f"(acc[2]), "+f"(acc[3])
        : "r"(a[0]), "r"(a[1]), "r"(a[2]), "r"(a[3]), "r"(b0), "r"(b1));
}
__device__ __forceinline__ void mma_f16(float acc[4], uint a0, uint a1, uint a2, uint a3,
                                        uint b0, uint b1) {
    asm volatile(
        "mma.sync.aligned.m16n8k16.row.col.f32.f16.f16.f32 "
        "{%0,%1,%2,%3}, {%4,%5,%6,%7}, {%8,%9}, {%0,%1,%2,%3};"
        : "+f"(acc[0]), "+f"(acc[1]), "+f"(acc[2]), "+f"(acc[3])
        : "r"(a0), "r"(a1), "r"(a2), "r"(a3), "r"(b0), "r"(b1));
}
__device__ __forceinline__ float2 h2f2(uint v) {
    __half2 h = *reinterpret_cast<__half2*>(&v);
    return __half22float2(h);
}

// ================= active-set construction ===================================
// marks store (compact index + 1); claim via CAS, finalize before kernel end.
__global__ void mark2_kernel(const int* __restrict__ nidx, int M) {
    int m = blockIdx.x * blockDim.x + threadIdx.x;
    if (m >= M) return;
    int d = nidx[m];
    if (atomicCAS(&g_mark2[d], 0, -1) == 0) {
        int p = atomicAdd(&g_n2, 1); g_list2[p] = d; g_mark2[d] = p + 1;
    }
    if (atomicCAS(&g_mark1[d], 0, -1) == 0) {
        int p = atomicAdd(&g_n1, 1); g_list1[p] = d; g_mark1[d] = p + 1;
    }
}

// T1 += sources of edges whose dst is in T2
__global__ void markS_kernel(const int* __restrict__ ei, int E) {
    int i = blockIdx.x * blockDim.x + threadIdx.x;
    if (i >= E) return;
    int d = ei[E + i];
    if (g_mark2[d]) {
        int s = ei[i];
        if (atomicCAS(&g_mark1[s], 0, -1) == 0) {
            int p = atomicAdd(&g_n1, 1); g_list1[p] = s; g_mark1[s] = p + 1;
        }
    }
}

// ================= compact CSR build (T1 segments only) =======================
__global__ void deg_kernel(const int* __restrict__ ei, int E) {
    int i = blockIdx.x * blockDim.x + threadIdx.x;
    if (i >= E) return;
    int m = g_mark1[ei[E + i]];
    if (m > 0) atomicAdd(&g_degc[m - 1], 1);
}

// grid scan stage A over T1-index space: exclusive scan of (deg+1)
__global__ __launch_bounds__(1024) void scanA_kernel() {
    __shared__ int wsum[32];
    const int n1 = g_n1;
    const int i = blockIdx.x * 1024 + threadIdx.x;
    const int lane = threadIdx.x & 31, wid = threadIdx.x >> 5;
    int v = (i < n1) ? (g_degc[i] + 1) : 0;
    int s = v;
    #pragma unroll
    for (int off = 1; off < 32; off <<= 1) {
        int t = __shfl_up_sync(0xffffffffu, s, off);
        if (lane >= off) s += t;
    }
    if (lane == 31) wsum[wid] = s;
    __syncthreads();
    if (wid == 0) {
        int ws = wsum[lane];
        #pragma unroll
        for (int off = 1; off < 32; off <<= 1) {
            int t = __shfl_up_sync(0xffffffffu, ws, off);
            if (lane >= off) ws += t;
        }
        wsum[lane] = ws;
    }
    __syncthreads();
    int excl = s - v + (wid ? wsum[wid - 1] : 0);
    if (i < n1) g_rowptr[i] = excl;
    if (threadIdx.x == 1023) g_bsum[blockIdx.x] = excl + v;
}

__global__ void scanB_kernel(int nb) {
    __shared__ int sh[128];
    const int t = threadIdx.x;
    int v = (t < nb) ? g_bsum[t] : 0;
    sh[t] = v;
    __syncthreads();
    for (int off = 1; off < 128; off <<= 1) {
        int x = (t >= off) ? sh[t - off] : 0;
        __syncthreads();
        sh[t] += x;
        __syncthreads();
    }
    g_bsum[t] = sh[t] - v;
    if (t == 127) {
        int total = sh[127];
        g_nasl1 = total;          // layer-1 active slots = ALL compact slots
        g_rowptr[g_n1] = total;
    }
}

__global__ __launch_bounds__(1024) void scanC_kernel() {
    const int n1 = g_n1;
    int i = blockIdx.x * 1024 + threadIdx.x;
    if (i < n1) {
        int rp = g_rowptr[i] + g_bsum[blockIdx.x];
        g_rowptr[i] = rp;
        g_cur[i]    = rp;
    }
}

// scatter + permute + fp16-convert edge attrs into COMPACT slot order.
__global__ void scatter_kernel(const int* __restrict__ ei, const float* __restrict__ ea, int E) {
    int i = blockIdx.x * blockDim.x + threadIdx.x;
    if (i >= E) return;
    int d = ei[E + i];
    int m = g_mark1[d];
    if (m <= 0) return;
    int s = ei[i];
    int pos = atomicAdd(&g_cur[m - 1], 1);
    g_csr_src[pos] = s;
    g_csr_dst[pos] = d;
    const float4* r4 = reinterpret_cast<const float4*>(ea) + (size_t)i * 8;
    __half2* dst = reinterpret_cast<__half2*>(g_eap + (size_t)pos * FE);
    #pragma unroll
    for (int q = 0; q < 8; ++q) {
        float4 v = r4[q];
        dst[2 * q]     = __floats2half2_rn(v.x, v.y);
        dst[2 * q + 1] = __floats2half2_rn(v.z, v.w);
    }
}

// layer-2 active slot list: slots of T2 segments
__global__ void build2_kernel() {
    const int lane = threadIdx.x & 31;
    const int gws = gridDim.x * 8;
    const int n2 = g_n2;
    for (int widx = blockIdx.x * 8 + (threadIdx.x >> 5); widx < n2; widx += gws) {
        int m = g_mark1[g_list2[widx]] - 1;
        int rp0 = g_rowptr[m], len = g_rowptr[m + 1] - rp0;
        int base;
        if (lane == 0) base = atomicAdd(&g_nasl2, len);
        base = __shfl_sync(0xffffffffu, base, 0);
        for (int k = lane; k < len; k += 32) g_asl2[base + k] = rp0 + k;
    }
}

// ---------------- self-loop attr: per-T1-segment mean ------------------------
__global__ void pre_csr_kernel() {
    const int lane = threadIdx.x & 31;
    const int gws = gridDim.x * 8;
    const int n1 = g_n1;
    for (int widx = blockIdx.x * 8 + (threadIdx.x >> 5); widx < n1; widx += gws) {
        const int d = g_list1[widx];
        const int rp0 = g_rowptr[widx], rp1 = g_rowptr[widx + 1];
        const int last = rp1 - 1;            // self-loop slot
        float s = 0.f;
        int e = rp0;
        for (; e + 4 <= last; e += 4) {
            float a0 = __half2float(g_eap[(size_t)(e + 0) * FE + lane]);
            float a1 = __half2float(g_eap[(size_t)(e + 1) * FE + lane]);
            float a2 = __half2float(g_eap[(size_t)(e + 2) * FE + lane]);
            float a3 = __half2float(g_eap[(size_t)(e + 3) * FE + lane]);
            s += (a0 + a1) + (a2 + a3);
        }
        for (; e < last; ++e) s += __half2float(g_eap[(size_t)e * FE + lane]);
        float mean = s / (float)max(last - rp0, 1);
        g_eap[(size_t)last * FE + lane] = __float2half_rn(mean);
        if (lane == 0) { g_csr_src[last] = d; g_csr_dst[last] = d; }
    }
}

// ---------------- single-output node linear via 3xTF32 tensor MMA ------------
// SET: 0 = full N, 1 = g_list1, 2 = g_list2. HPREV: read g_out+bias1+relu.
// right: 0 -> g_xlh, 1 -> g_xrh. Block = 128 nodes, 8 warps x 16 rows.
template<int IN, int SET, bool HPREV>
__global__ __launch_bounds__(256) void lin_mma_kernel(
        const float* __restrict__ inp, const float* __restrict__ W,
        const float* __restrict__ bias, const float* __restrict__ prevBias,
        int N, int right) {
    const int nlim = (SET == 0) ? N : (SET == 1 ? g_n1 : g_n2);
    const int nb = blockIdx.x * 128;
    if (nb >= nlim) return;

    constexpr int KC = 16;
    __shared__ uint XsH[128][20], XsL[128][20];
    __shared__ uint WsH[KC][68],  WsL[KC][68];

    const int t = threadIdx.x;
    const int lane = t & 31;
    const int mt = t >> 5;                   // warp = m-tile 0..7
    const int g = lane >> 2, c = lane & 3;

    float acc[8][4];
    #pragma unroll
    for (int nt = 0; nt < 8; ++nt) {
        acc[nt][0] = acc[nt][1] = acc[nt][2] = acc[nt][3] = 0.f;
    }

    for (int kc = 0; kc < IN; kc += KC) {
        __syncthreads();
        for (int idx = t; idx < 128 * KC; idx += 256) {
            int row = idx / KC, col = idx - row * KC;
            int m = nb + row;
            float v = 0.f;
            if (m < nlim) {
                int node = (SET == 0) ? m : (SET == 1 ? g_list1[m] : g_list2[m]);
                int j = kc + col;
                if (HPREV) v = fmaxf(g_out[(size_t)node * HID + j] + prevBias[j], 0.f);
                else       v = inp[(size_t)node * IN + j];
            }
            uint hb, lb; tf32_split(v, hb, lb);
            XsH[row][col] = hb; XsL[row][col] = lb;
        }
        for (int idx = t; idx < KC * 64; idx += 256) {
            int row = idx >> 6, col = idx & 63;
            float v = W[(kc + row) * HID + col];
            uint hb, lb; tf32_split(v, hb, lb);
            WsH[row][col] = hb; WsL[row][col] = lb;
        }
        __syncthreads();
        #pragma unroll
        for (int kk = 0; kk < KC; kk += 8) {
            uint aH[4], aL[4];
            aH[0] = XsH[mt * 16 + g    ][kk + c];
            aH[1] = XsH[mt * 16 + g + 8][kk + c];
            aH[2] = XsH[mt * 16 + g    ][kk + c + 4];
            aH[3] = XsH[mt * 16 + g + 8][kk + c + 4];
            aL[0] = XsL[mt * 16 + g    ][kk + c];
            aL[1] = XsL[mt * 16 + g + 8][kk + c];
            aL[2] = XsL[mt * 16 + g    ][kk + c + 4];
            aL[3] = XsL[mt * 16 + g + 8][kk + c + 4];
            #pragma unroll
            for (int nt = 0; nt < 8; ++nt) {
                int col = nt * 8 + g;
                uint bH0 = WsH[kk + c    ][col];
                uint bH1 = WsH[kk + c + 4][col];
                uint bL0 = WsL[kk + c    ][col];
                uint bL1 = WsL[kk + c + 4][col];
                mma_tf32(acc[nt], aH, bH0, bH1);
                mma_tf32(acc[nt], aL, bH0, bH1);
                mma_tf32(acc[nt], aH, bL0, bL1);
            }
        }
    }

    uint* dsth = reinterpret_cast<uint*>(right ? g_xrh : g_xlh);
    const int m0 = nb + mt * 16 + g;
    const int m1 = m0 + 8;
    const int node0 = (m0 < nlim) ? ((SET == 0) ? m0 : (SET == 1 ? g_list1[m0] : g_list2[m0])) : -1;
    const int node1 = (m1 < nlim) ? ((SET == 0) ? m1 : (SET == 1 ? g_list1[m1] : g_list2[m1])) : -1;
    #pragma unroll
    for (int nt = 0; nt < 8; ++nt) {
        int colL = nt * 8 + 2 * c;
        float bx = bias[colL], by = bias[colL + 1];
        if (node0 >= 0) {
            __half2 h = __floats2half2_rn(acc[nt][0] + bx, acc[nt][1] + by);
            dsth[(size_t)node0 * 32 + nt * 4 + c] = *reinterpret_cast<uint*>(&h);
        }
        if (node1 >= 0) {
            __half2 h = __floats2half2_rn(acc[nt][2] + bx, acc[nt][3] + by);
            dsth[(size_t)node1 * 32 + nt * 4 + c] = *reinterpret_cast<uint*>(&h);
        }
    }
}

// ---------------- edge pass A: fp16 MMA e-GEMM + logits over active slots ----
// layer 1: slots are 0..g_nasl1 (identity, fully sequential); layer 2: g_asl2.
__global__ __launch_bounds__(256) void edgeA_kernel(
        const float* __restrict__ We, const float* __restrict__ att, int layer) {
    const int nasl = (layer == 1) ? g_nasl1 : g_nasl2;

    const int t = threadIdx.x;
    const int lane = t & 31;
    const int w = t >> 5;
    const int g = lane >> 2;                 // row group 0..7
    const int c = lane & 3;                  // col-in-group 0..3
    const int nTiles = (nasl + 15) >> 4;
    const int gw = blockIdx.x * 8 + w;
    const int gws = gridDim.x * 8;

    // preload B fragments (We as fp16) and att pairs into registers
    uint breg[8][2][2];
    float2 areg[8];
    #pragma unroll
    for (int nt = 0; nt < 8; ++nt) {
        const int n = nt * 8 + g;
        #pragma unroll
        for (int ks = 0; ks < 2; ++ks) {
            int k0 = ks * 16 + 2 * c;
            __half2 lo = __floats2half2_rn(We[k0 * HID + n],       We[(k0 + 1) * HID + n]);
            __half2 hi = __floats2half2_rn(We[(k0 + 8) * HID + n], We[(k0 + 9) * HID + n]);
            breg[nt][ks][0] = *reinterpret_cast<uint*>(&lo);
            breg[nt][ks][1] = *reinterpret_cast<uint*>(&hi);
        }
        areg[nt] = reinterpret_cast<const float2*>(att)[nt * 4 + c];
    }

    const uint* xlh = reinterpret_cast<const uint*>(g_xlh);
    const uint* xrh = reinterpret_cast<const uint*>(g_xrh);

    for (int tile = gw; tile < nTiles; tile += gws) {
        const int iA = tile * 16 + g;
        const int iB = iA + 8;
        int rowA = MAXET, rowB = MAXET;       // pad row: zeros, never written
        if (iA < nasl) rowA = (layer == 1) ? iA : g_asl2[iA];
        if (iB < nasl) rowB = (layer == 1) ? iB : g_asl2[iB];

        const int sA = g_csr_src[rowA], dA = g_csr_dst[rowA];
        const int sB = g_csr_src[rowB], dB = g_csr_dst[rowB];
        const uint* pA = reinterpret_cast<const uint*>(g_eap + (size_t)rowA * FE);
        const uint* pB = reinterpret_cast<const uint*>(g_eap + (size_t)rowB * FE);

        uint afr[2][4];
        #pragma unroll
        for (int ks = 0; ks < 2; ++ks) {
            afr[ks][0] = pA[ks * 8 + c];
            afr[ks][1] = pB[ks * 8 + c];
            afr[ks][2] = pA[ks * 8 + c + 4];
            afr[ks][3] = pB[ks * 8 + c + 4];
        }

        float partA = 0.f, partB = 0.f;
        #pragma unroll
        for (int nt = 0; nt < 8; ++nt) {
            float acc[4] = {0.f, 0.f, 0.f, 0.f};
            mma_f16(acc, afr[0][0], afr[0][1], afr[0][2], afr[0][3],
                    breg[nt][0][0], breg[nt][0][1]);
            mma_f16(acc, afr[1][0], afr[1][1], afr[1][2], afr[1][3],
                    breg[nt][1][0], breg[nt][1][1]);
            float2 xlA = h2f2(xlh[(size_t)sA * 32 + nt * 4 + c]);
            float2 xrA = h2f2(xrh[(size_t)dA * 32 + nt * 4 + c]);
            float2 xlB = h2f2(xlh[(size_t)sB * 32 + nt * 4 + c]);
            float2 xrB = h2f2(xrh[(size_t)dB * 32 + nt * 4 + c]);
            float u0 = acc[0] + xlA.x + xrA.x;
            float u1 = acc[1] + xlA.y + xrA.y;
            float u2 = acc[2] + xlB.x + xrB.x;
            float u3 = acc[3] + xlB.y + xrB.y;
            u0 = fmaxf(u0, 0.f) + 0.2f * fminf(u0, 0.f);
            u1 = fmaxf(u1, 0.f) + 0.2f * fminf(u1, 0.f);
            u2 = fmaxf(u2, 0.f) + 0.2f * fminf(u2, 0.f);
            u3 = fmaxf(u3, 0.f) + 0.2f * fminf(u3, 0.f);
            partA = fmaf(u0, areg[nt].x, fmaf(u1, areg[nt].y, partA));
            partB = fmaf(u2, areg[nt].x, fmaf(u3, areg[nt].y, partB));
        }
        partA += __shfl_xor_sync(0xffffffffu, partA, 1);
        partA += __shfl_xor_sync(0xffffffffu, partA, 2);
        partB += __shfl_xor_sync(0xffffffffu, partB, 1);
        partB += __shfl_xor_sync(0xffffffffu, partB, 2);
        if (c == 0) {
            if (iA < nasl) g_exc[rowA] = __expf(partA);
            if (iB < nasl) g_exc[rowB] = __expf(partB);
        }
    }
}

// ---------------- edge pass B: softmax-normalize + aggregate (listed nodes) --
__global__ __launch_bounds__(256) void edgeB_kernel(int layer) {
    const int n = (layer == 1) ? g_n1 : g_n2;
    const int lane = threadIdx.x & 31;
    const int gws = gridDim.x * 8;
    const uint* xlh = reinterpret_cast<const uint*>(g_xlh);

    for (int widx = blockIdx.x * 8 + (threadIdx.x >> 5); widx < n; widx += gws) {
        int d, m;
        if (layer == 1) { d = g_list1[widx]; m = widx; }
        else            { d = g_list2[widx]; m = g_mark1[d] - 1; }
        const int rp0 = g_rowptr[m], rp1 = g_rowptr[m + 1];

        float den = 0.f;
        for (int e = rp0 + lane; e < rp1; e += 32) den += g_exc[e];
        #pragma unroll
        for (int off = 16; off > 0; off >>= 1)
            den += __shfl_xor_sync(0xffffffffu, den, off);
        const float inv = 1.f / den;

        float ax = 0.f, ay = 0.f;
        int e = rp0;
        for (; e + 4 <= rp1; e += 4) {
            int s0 = g_csr_src[e],     s1 = g_csr_src[e + 1];
            int s2 = g_csr_src[e + 2], s3 = g_csr_src[e + 3];
            float w0 = g_exc[e],     w1 = g_exc[e + 1];
            float w2 = g_exc[e + 2], w3 = g_exc[e + 3];
            float2 v0 = h2f2(xlh[(size_t)s0 * 32 + lane]);
            float2 v1 = h2f2(xlh[(size_t)s1 * 32 + lane]);
            float2 v2 = h2f2(xlh[(size_t)s2 * 32 + lane]);
            float2 v3 = h2f2(xlh[(size_t)s3 * 32 + lane]);
            ax = fmaf(w0, v0.x, fmaf(w1, v1.x, fmaf(w2, v2.x, fmaf(w3, v3.x, ax))));
            ay = fmaf(w0, v0.y, fmaf(w1, v1.y, fmaf(w2, v2.y, fmaf(w3, v3.y, ay))));
        }
        for (; e < rp1; ++e) {
            int s = g_csr_src[e];
            float wgt = g_exc[e];
            float2 xv = h2f2(xlh[(size_t)s * 32 + lane]);
            ax = fmaf(wgt, xv.x, ax);
            ay = fmaf(wgt, xv.y, ay);
        }
        float2* out2 = reinterpret_cast<float2*>(g_out);
        out2[(size_t)d * 32 + lane] = make_float2(ax * inv, ay * inv);
    }
}

// ---------------- final MLP at node_idx + restore zero-invariants ------------
__global__ void fin_kernel(const int* __restrict__ idx, const float* __restrict__ bias2,
                           const float* __restrict__ y,
                           const float* __restrict__ W0, const float* __restrict__ b0,
                           const float* __restrict__ W1, const float* __restrict__ b1,
                           const float* __restrict__ W2, const float* __restrict__ b2,
                           float* __restrict__ dout, int M, int rf, int N) {
    // restore zero-invariants for the next launch (graph replay safe)
    int tid = blockIdx.x * blockDim.x + threadIdx.x;
    for (int z = tid; z < N; z += gridDim.x * blockDim.x) {
        g_degc[z] = 0; g_mark1[z] = 0; g_mark2[z] = 0;
    }
    if (tid == 0) { g_n1 = 0; g_n2 = 0; g_nasl1 = 0; g_nasl2 = 0; }

    __shared__ float sh[4][64];
    __shared__ float sz[4][32];
    const int w = threadIdx.x >> 5, lane = threadIdx.x & 31;
    const int m = blockIdx.x * 4 + w;
    if (m >= M) return;
    const int v = idx[m];

    float h0 = fmaxf(g_out[(size_t)v * HID + lane]      + bias2[lane],      0.f);
    float h1 = fmaxf(g_out[(size_t)v * HID + 32 + lane] + bias2[32 + lane], 0.f);
    sh[w][lane] = h0; sh[w][32 + lane] = h1;
    __syncwarp();

    int k = v / rf;
    float y0 = y[2 * k], y1 = y[2 * k + 1];
    float q0 = fmaxf(y0 * W0[0] + y1 * W0[2] + b0[0], 0.f);
    float q1 = fmaxf(y0 * W0[1] + y1 * W0[3] + b0[1], 0.f);

    float z = b1[lane];
    #pragma unroll
    for (int j = 0; j < 64; ++j) z += sh[w][j] * W1[j * 32 + lane];
    z += q0 * W1[64 * 32 + lane] + q1 * W1[65 * 32 + lane];
    z = fmaxf(z, 0.f);
    sz[w][lane] = z;
    __syncwarp();

    float o = b2[lane];
    #pragma unroll
    for (int j = 0; j < 32; ++j) o += sz[w][j] * W2[j * 32 + lane];
    dout[m * 32 + lane] = o;
}

// ---------------- launch ------------------------------------------------------
extern "C" void kernel_launch(void* const* d_in, const int* in_sizes, int n_in,
                              void* d_out, int out_size) {
    const float* x    = (const float*)d_in[0];
    const float* ea   = (const float*)d_in[1];
    const float* y    = (const float*)d_in[2];
    const float* Wl1  = (const float*)d_in[3];
    const float* bl1  = (const float*)d_in[4];
    const float* Wr1  = (const float*)d_in[5];
    const float* br1  = (const float*)d_in[6];
    const float* We1  = (const float*)d_in[7];
    const float* att1 = (const float*)d_in[8];
    const float* bias1= (const float*)d_in[9];
    const float* Wl2  = (const float*)d_in[10];
    const float* bl2  = (const float*)d_in[11];
    const float* Wr2  = (const float*)d_in[12];
    const float* br2  = (const float*)d_in[13];
    const float* We2  = (const float*)d_in[14];
    const float* att2 = (const float*)d_in[15];
    const float* bias2= (const float*)d_in[16];
    const float* W0   = (const float*)d_in[17];
    const float* b0   = (const float*)d_in[18];
    const float* W1   = (const float*)d_in[19];
    const float* b1   = (const float*)d_in[20];
    const float* W2   = (const float*)d_in[21];
    const float* b2   = (const float*)d_in[22];
    const int*   ei   = (const int*)  d_in[23];
    const int*   nidx = (const int*)  d_in[24];

    const int N    = in_sizes[0] / FN;
    const int E    = in_sizes[23] / 2;
    const int M    = in_sizes[24];
    const int NG   = in_sizes[2] / 2;
    const int rf   = N / NG;

    const int EBLK = (E + 255) / 256;
    const int NB1K = (N + 1023) / 1024;
    const int LINB = (N + 127) / 128;

    // ---- active sets ----
    mark2_kernel   <<<(M + 255) / 256, 256>>>(nidx, M);
    markS_kernel   <<<EBLK, 256>>>(ei, E);

    // ---- compact CSR over T1 ----
    deg_kernel     <<<EBLK, 256>>>(ei, E);
    scanA_kernel   <<<NB1K, 1024>>>();
    scanB_kernel   <<<1, 128>>>(NB1K);
    scanC_kernel   <<<NB1K, 1024>>>();
    scatter_kernel <<<EBLK, 256>>>(ei, ea, E);
    build2_kernel  <<<128, 256>>>();
    pre_csr_kernel <<<512, 256>>>();

    // ---- layer 1: xl over all N, xr over T1 ----
    lin_mma_kernel<FN, 0, false><<<LINB, 256>>>(x, Wl1, bl1, nullptr, N, 0);
    lin_mma_kernel<FN, 1, false><<<LINB, 256>>>(x, Wr1, br1, nullptr, N, 1);
    edgeA_kernel<<<2048, 256>>>(We1, att1, 1);
    edgeB_kernel<<<1024, 256>>>(1);

    // ---- layer 2: xl over T1, xr over T2 ----
    lin_mma_kernel<HID, 1, true><<<LINB, 256>>>(x, Wl2, bl2, bias1, N, 0);
    lin_mma_kernel<HID, 2, true><<<LINB, 256>>>(x, Wr2, br2, bias1, N, 1);
    edgeA_kernel<<<512, 256>>>(We2, att2, 2);
    edgeB_kernel<<<256, 256>>>(2);

    // ---- final MLP at node_idx (also restores zero-invariants) ----
    fin_kernel<<<512, 128>>>(nidx, bias2, y, W0, b0, W1, b1, W2, b2,
                             (float*)d_out, M, rf, N);
}

// round 12
// speedup vs baseline: 3.5169x; 1.1014x over previous
#include <cuda_runtime.h>
#include <cuda_fp16.h>
#include <cstddef>

typedef unsigned long long ull;
typedef unsigned int uint;

// ---------------- problem constants (shapes fixed by the dataset) -----------
#define MAXN 100000
#define MAXE 1600000
#define MAXET (MAXE + MAXN)
#define MAXETP (MAXET + 16)   // padded (edgeA tile overrun reads zero row)
#define FN   128     // node feature dim (layer1 input)
#define FE   32      // edge feature dim
#define HID  64

// ---------------- device scratch (static: no allocation allowed) ------------
__device__ __align__(16) __half g_xlh[MAXN * HID];  // source-side transform (fp16)
__device__ __align__(16) __half g_xrh[MAXN * HID];  // target-side transform (fp16)
__device__ float  g_exc [MAXETP];           // exp(logit), compact CSR slot order
__device__ float  g_out [MAXN * HID];       // layer output (valid at T1 nodes)
__device__ int    g_degc[MAXN];             // degree per T1 index (zero at entry)
__device__ int    g_mark1[MAXN];            // T1 index+1, 0 = inactive (zeroed by fin)
__device__ int    g_mark2[MAXN];            // T2 index+1, 0 = inactive (zeroed by fin)
__device__ int    g_rowptr[MAXN + 1];       // compact rowptr over T1 indices
__device__ int    g_cur [MAXN];
__device__ int    g_bsum[128];
__device__ int    g_csr_src[MAXETP];        // src node per compact slot
__device__ int    g_csr_dst[MAXETP];        // dst node per compact slot
__device__ int    g_list1[MAXN];            // compacted T1 node list
__device__ int    g_list2[MAXN];            // compacted T2 node list
__device__ int    g_asl2[MAXETP];           // active compact slots, layer 2
__device__ int2   g_pair_es[MAXET];         // (eid, src) of accepted edges
__device__ int2   g_pair_md[MAXET];         // (T1 idx, dst) of accepted edges
__device__ int    g_n1, g_n2, g_nasl1, g_nasl2, g_np;  // zero at entry (fin restores)
__device__ __align__(16) __half g_eap[(size_t)MAXETP * FE];  // permuted fp16 edge attrs

// ---------------- small helpers ---------------------------------------------
__device__ __forceinline__ void mma_f16(float acc[4], uint a0, uint a1, uint a2, uint a3,
                                        uint b0, uint b1) {
    asm volatile(
        "mma.sync.aligned.m16n8k16.row.col.f32.f16.f16.f32 "
        "{%0,%1,%2,%3}, {%4,%5,%6,%7}, {%8,%9}, {%0,%1,%2,%3};"
        : "+f"(acc[0]), "+f"(acc[1]), "+f"(acc[2]), "+f"(acc[3])
        : "r"(a0), "r"(a1), "r"(a2), "r"(a3), "r"(b0), "r"(b1));
}
__device__ __forceinline__ float2 h2f2(uint v) {
    __half2 h = *reinterpret_cast<__half2*>(&v);
    return __half22float2(h);
}
__device__ __forceinline__ uint f2h2(float x, float y) {
    __half2 h = __floats2half2_rn(x, y);
    return *reinterpret_cast<uint*>(&h);
}

// ================= active-set construction ===================================
__global__ void mark2_kernel(const int* __restrict__ nidx, int M) {
    int m = blockIdx.x * blockDim.x + threadIdx.x;
    if (m >= M) return;
    int d = nidx[m];
    if (atomicCAS(&g_mark2[d], 0, -1) == 0) {
        int p = atomicAdd(&g_n2, 1); g_list2[p] = d; g_mark2[d] = p + 1;
    }
    if (atomicCAS(&g_mark1[d], 0, -1) == 0) {
        int p = atomicAdd(&g_n1, 1); g_list1[p] = d; g_mark1[d] = p + 1;
    }
}

// T1 += sources of edges whose dst is in T2
__global__ void markS_kernel(const int* __restrict__ ei, int E) {
    int i = blockIdx.x * blockDim.x + threadIdx.x;
    if (i >= E) return;
    int d = ei[E + i];
    if (g_mark2[d]) {
        int s = ei[i];
        if (atomicCAS(&g_mark1[s], 0, -1) == 0) {
            int p = atomicAdd(&g_n1, 1); g_list1[p] = s; g_mark1[s] = p + 1;
        }
    }
}

// ================= compact CSR build (T1 segments only) =======================
// Single E-scan: filter + append pairs + degree count.
__global__ void collect_kernel(const int* __restrict__ ei, int E) {
    int i = blockIdx.x * blockDim.x + threadIdx.x;
    if (i >= E) return;
    int d = ei[E + i];
    int m = g_mark1[d];
    if (m <= 0) return;
    int j = atomicAdd(&g_np, 1);
    g_pair_es[j] = make_int2(i, ei[i]);
    g_pair_md[j] = make_int2(m - 1, d);
    atomicAdd(&g_degc[m - 1], 1);
}

// grid scan stage A over T1-index space: exclusive scan of (deg+1)
__global__ __launch_bounds__(1024) void scanA_kernel() {
    __shared__ int wsum[32];
    const int n1 = g_n1;
    const int i = blockIdx.x * 1024 + threadIdx.x;
    const int lane = threadIdx.x & 31, wid = threadIdx.x >> 5;
    int v = (i < n1) ? (g_degc[i] + 1) : 0;
    int s = v;
    #pragma unroll
    for (int off = 1; off < 32; off <<= 1) {
        int t = __shfl_up_sync(0xffffffffu, s, off);
        if (lane >= off) s += t;
    }
    if (lane == 31) wsum[wid] = s;
    __syncthreads();
    if (wid == 0) {
        int ws = wsum[lane];
        #pragma unroll
        for (int off = 1; off < 32; off <<= 1) {
            int t = __shfl_up_sync(0xffffffffu, ws, off);
            if (lane >= off) ws += t;
        }
        wsum[lane] = ws;
    }
    __syncthreads();
    int excl = s - v + (wid ? wsum[wid - 1] : 0);
    if (i < n1) g_rowptr[i] = excl;
    if (threadIdx.x == 1023) g_bsum[blockIdx.x] = excl + v;
}

__global__ void scanB_kernel(int nb) {
    __shared__ int sh[128];
    const int t = threadIdx.x;
    int v = (t < nb) ? g_bsum[t] : 0;
    sh[t] = v;
    __syncthreads();
    for (int off = 1; off < 128; off <<= 1) {
        int x = (t >= off) ? sh[t - off] : 0;
        __syncthreads();
        sh[t] += x;
        __syncthreads();
    }
    g_bsum[t] = sh[t] - v;
    if (t == 127) {
        int total = sh[127];
        g_nasl1 = total;          // layer-1 active slots = ALL compact slots
        g_rowptr[g_n1] = total;
    }
}

__global__ __launch_bounds__(1024) void scanC_kernel() {
    const int n1 = g_n1;
    int i = blockIdx.x * 1024 + threadIdx.x;
    if (i < n1) {
        int rp = g_rowptr[i] + g_bsum[blockIdx.x];
        g_rowptr[i] = rp;
        g_cur[i]    = rp;
    }
}

// place accepted edges into compact slots + permute/convert edge attrs
__global__ void place_kernel(const float* __restrict__ ea) {
    const int np = g_np;
    const int stride = gridDim.x * blockDim.x;
    for (int j = blockIdx.x * blockDim.x + threadIdx.x; j < np; j += stride) {
        int2 es = g_pair_es[j];
        int2 md = g_pair_md[j];
        int pos = atomicAdd(&g_cur[md.x], 1);
        g_csr_src[pos] = es.y;
        g_csr_dst[pos] = md.y;
        const float4* r4 = reinterpret_cast<const float4*>(ea) + (size_t)es.x * 8;
        __half2* dst = reinterpret_cast<__half2*>(g_eap + (size_t)pos * FE);
        #pragma unroll
        for (int q = 0; q < 8; ++q) {
            float4 v = r4[q];
            dst[2 * q]     = __floats2half2_rn(v.x, v.y);
            dst[2 * q + 1] = __floats2half2_rn(v.z, v.w);
        }
    }
}

// merged: self-loop mean per T1 segment  +  layer-2 active slot list
__global__ void prep_kernel() {
    const int lane = threadIdx.x & 31;
    const int gws = gridDim.x * 8;
    const int wbase = blockIdx.x * 8 + (threadIdx.x >> 5);
    const int n1 = g_n1;
    for (int widx = wbase; widx < n1; widx += gws) {
        const int d = g_list1[widx];
        const int rp0 = g_rowptr[widx], rp1 = g_rowptr[widx + 1];
        const int last = rp1 - 1;            // self-loop slot
        float s = 0.f;
        int e = rp0;
        for (; e + 4 <= last; e += 4) {
            float a0 = __half2float(g_eap[(size_t)(e + 0) * FE + lane]);
            float a1 = __half2float(g_eap[(size_t)(e + 1) * FE + lane]);
            float a2 = __half2float(g_eap[(size_t)(e + 2) * FE + lane]);
            float a3 = __half2float(g_eap[(size_t)(e + 3) * FE + lane]);
            s += (a0 + a1) + (a2 + a3);
        }
        for (; e < last; ++e) s += __half2float(g_eap[(size_t)e * FE + lane]);
        float mean = s / (float)max(last - rp0, 1);
        g_eap[(size_t)last * FE + lane] = __float2half_rn(mean);
        if (lane == 0) { g_csr_src[last] = d; g_csr_dst[last] = d; }
    }
    const int n2 = g_n2;
    for (int widx = wbase; widx < n2; widx += gws) {
        int m = g_mark1[g_list2[widx]] - 1;
        int rp0 = g_rowptr[m], len = g_rowptr[m + 1] - rp0;
        int base;
        if (lane == 0) base = atomicAdd(&g_nasl2, len);
        base = __shfl_sync(0xffffffffu, base, 0);
        for (int k = lane; k < len; k += 32) g_asl2[base + k] = rp0 + k;
    }
}

// ---------------- single-output node linear via fp16 tensor MMA --------------
// SET: 0 = full N, 1 = g_list1, 2 = g_list2. HPREV: read g_out+bias1+relu.
// right: 0 -> g_xlh, 1 -> g_xrh. Block = 128 nodes, 8 warps x 16 rows.
template<int IN, int SET, bool HPREV>
__global__ __launch_bounds__(256) void lin_f16_kernel(
        const float* __restrict__ inp, const float* __restrict__ W,
        const float* __restrict__ bias, const float* __restrict__ prevBias,
        int N, int right) {
    const int nlim = (SET == 0) ? N : (SET == 1 ? g_n1 : g_n2);
    const int nb = blockIdx.x * 128;
    if (nb >= nlim) return;

    constexpr int KC = 16;                    // k per iteration (one k16 MMA step)
    __shared__ uint Xs[128][9];               // 8 k-pair words + pad
    __shared__ uint Ws[8][68];                // k-pair word x 64 cols + pad

    const int t = threadIdx.x;
    const int lane = t & 31;
    const int mt = t >> 5;                    // warp = m-tile 0..7
    const int g = lane >> 2, c = lane & 3;

    float acc[8][4];
    #pragma unroll
    for (int nt = 0; nt < 8; ++nt) {
        acc[nt][0] = acc[nt][1] = acc[nt][2] = acc[nt][3] = 0.f;
    }

    for (int kc = 0; kc < IN; kc += KC) {
        __syncthreads();
        // stage X chunk: 128 rows x 8 half2 words
        for (int idx = t; idx < 128 * 8; idx += 256) {
            int row = idx >> 3, kw = idx & 7;
            int m = nb + row;
            float v0 = 0.f, v1 = 0.f;
            if (m < nlim) {
                int node = (SET == 0) ? m : (SET == 1 ? g_list1[m] : g_list2[m]);
                int j = kc + 2 * kw;
                if (HPREV) {
                    float2 hv = *reinterpret_cast<const float2*>(g_out + (size_t)node * HID + j);
                    v0 = fmaxf(hv.x + prevBias[j], 0.f);
                    v1 = fmaxf(hv.y + prevBias[j + 1], 0.f);
                } else {
                    float2 xv = *reinterpret_cast<const float2*>(inp + (size_t)node * IN + j);
                    v0 = xv.x; v1 = xv.y;
                }
            }
            Xs[row][kw] = f2h2(v0, v1);
        }
        // stage W chunk: 8 k-pair words x 64 cols
        for (int idx = t; idx < 8 * 64; idx += 256) {
            int kw = idx >> 6, col = idx & 63;
            int k = kc + 2 * kw;
            Ws[kw][col] = f2h2(W[k * HID + col], W[(k + 1) * HID + col]);
        }
        __syncthreads();
        uint a0 = Xs[mt * 16 + g    ][c];
        uint a1 = Xs[mt * 16 + g + 8][c];
        uint a2 = Xs[mt * 16 + g    ][c + 4];
        uint a3 = Xs[mt * 16 + g + 8][c + 4];
        #pragma unroll
        for (int nt = 0; nt < 8; ++nt) {
            int col = nt * 8 + g;
            mma_f16(acc[nt], a0, a1, a2, a3, Ws[c][col], Ws[c + 4][col]);
        }
    }

    uint* dsth = reinterpret_cast<uint*>(right ? g_xrh : g_xlh);
    const int m0 = nb + mt * 16 + g;
    const int m1 = m0 + 8;
    const int node0 = (m0 < nlim) ? ((SET == 0) ? m0 : (SET == 1 ? g_list1[m0] : g_list2[m0])) : -1;
    const int node1 = (m1 < nlim) ? ((SET == 0) ? m1 : (SET == 1 ? g_list1[m1] : g_list2[m1])) : -1;
    #pragma unroll
    for (int nt = 0; nt < 8; ++nt) {
        int colL = nt * 8 + 2 * c;
        float bx = bias[colL], by = bias[colL + 1];
        if (node0 >= 0)
            dsth[(size_t)node0 * 32 + nt * 4 + c] = f2h2(acc[nt][0] + bx, acc[nt][1] + by);
        if (node1 >= 0)
            dsth[(size_t)node1 * 32 + nt * 4 + c] = f2h2(acc[nt][2] + bx, acc[nt][3] + by);
    }
}

// ---------------- edge pass A: fp16 MMA e-GEMM + logits over active slots ----
// layer 1: slots are 0..g_nasl1 (identity, fully sequential); layer 2: g_asl2.
__global__ __launch_bounds__(256) void edgeA_kernel(
        const float* __restrict__ We, const float* __restrict__ att, int layer) {
    const int nasl = (layer == 1) ? g_nasl1 : g_nasl2;

    const int t = threadIdx.x;
    const int lane = t & 31;
    const int w = t >> 5;
    const int g = lane >> 2;                 // row group 0..7
    const int c = lane & 3;                  // col-in-group 0..3
    const int nTiles = (nasl + 15) >> 4;
    const int gw = blockIdx.x * 8 + w;
    const int gws = gridDim.x * 8;

    // preload B fragments (We as fp16) and att pairs into registers
    uint breg[8][2][2];
    float2 areg[8];
    #pragma unroll
    for (int nt = 0; nt < 8; ++nt) {
        const int n = nt * 8 + g;
        #pragma unroll
        for (int ks = 0; ks < 2; ++ks) {
            int k0 = ks * 16 + 2 * c;
            breg[nt][ks][0] = f2h2(We[k0 * HID + n],       We[(k0 + 1) * HID + n]);
            breg[nt][ks][1] = f2h2(We[(k0 + 8) * HID + n], We[(k0 + 9) * HID + n]);
        }
        areg[nt] = reinterpret_cast<const float2*>(att)[nt * 4 + c];
    }

    const uint* xlh = reinterpret_cast<const uint*>(g_xlh);
    const uint* xrh = reinterpret_cast<const uint*>(g_xrh);

    for (int tile = gw; tile < nTiles; tile += gws) {
        const int iA = tile * 16 + g;
        const int iB = iA + 8;
        int rowA = MAXET, rowB = MAXET;       // pad row: zeros, never written
        if (iA < nasl) rowA = (layer == 1) ? iA : g_asl2[iA];
        if (iB < nasl) rowB = (layer == 1) ? iB : g_asl2[iB];

        const int sA = g_csr_src[rowA], dA = g_csr_dst[rowA];
        const int sB = g_csr_src[rowB], dB = g_csr_dst[rowB];
        const uint* pA = reinterpret_cast<const uint*>(g_eap + (size_t)rowA * FE);
        const uint* pB = reinterpret_cast<const uint*>(g_eap + (size_t)rowB * FE);

        uint afr[2][4];
        #pragma unroll
        for (int ks = 0; ks < 2; ++ks) {
            afr[ks][0] = pA[ks * 8 + c];
            afr[ks][1] = pB[ks * 8 + c];
            afr[ks][2] = pA[ks * 8 + c + 4];
            afr[ks][3] = pB[ks * 8 + c + 4];
        }

        float partA = 0.f, partB = 0.f;
        #pragma unroll
        for (int nt = 0; nt < 8; ++nt) {
            float acc[4] = {0.f, 0.f, 0.f, 0.f};
            mma_f16(acc, afr[0][0], afr[0][1], afr[0][2], afr[0][3],
                    breg[nt][0][0], breg[nt][0][1]);
            mma_f16(acc, afr[1][0], afr[1][1], afr[1][2], afr[1][3],
                    breg[nt][1][0], breg[nt][1][1]);
            float2 xlA = h2f2(xlh[(size_t)sA * 32 + nt * 4 + c]);
            float2 xrA = h2f2(xrh[(size_t)dA * 32 + nt * 4 + c]);
            float2 xlB = h2f2(xlh[(size_t)sB * 32 + nt * 4 + c]);
            float2 xrB = h2f2(xrh[(size_t)dB * 32 + nt * 4 + c]);
            float u0 = acc[0] + xlA.x + xrA.x;
            float u1 = acc[1] + xlA.y + xrA.y;
            float u2 = acc[2] + xlB.x + xrB.x;
            float u3 = acc[3] + xlB.y + xrB.y;
            u0 = fmaxf(u0, 0.f) + 0.2f * fminf(u0, 0.f);
            u1 = fmaxf(u1, 0.f) + 0.2f * fminf(u1, 0.f);
            u2 = fmaxf(u2, 0.f) + 0.2f * fminf(u2, 0.f);
            u3 = fmaxf(u3, 0.f) + 0.2f * fminf(u3, 0.f);
            partA = fmaf(u0, areg[nt].x, fmaf(u1, areg[nt].y, partA));
            partB = fmaf(u2, areg[nt].x, fmaf(u3, areg[nt].y, partB));
        }
        partA += __shfl_xor_sync(0xffffffffu, partA, 1);
        partA += __shfl_xor_sync(0xffffffffu, partA, 2);
        partB += __shfl_xor_sync(0xffffffffu, partB, 1);
        partB += __shfl_xor_sync(0xffffffffu, partB, 2);
        if (c == 0) {
            if (iA < nasl) g_exc[rowA] = __expf(partA);
            if (iB < nasl) g_exc[rowB] = __expf(partB);
        }
    }
}

// ---------------- edge pass B: softmax-normalize + aggregate (listed nodes) --
__global__ __launch_bounds__(256) void edgeB_kernel(int layer) {
    const int n = (layer == 1) ? g_n1 : g_n2;
    const int lane = threadIdx.x & 31;
    const int gws = gridDim.x * 8;
    const uint* xlh = reinterpret_cast<const uint*>(g_xlh);

    for (int widx = blockIdx.x * 8 + (threadIdx.x >> 5); widx < n; widx += gws) {
        int d, m;
        if (layer == 1) { d = g_list1[widx]; m = widx; }
        else            { d = g_list2[widx]; m = g_mark1[d] - 1; }
        const int rp0 = g_rowptr[m], rp1 = g_rowptr[m + 1];

        float den = 0.f;
        for (int e = rp0 + lane; e < rp1; e += 32) den += g_exc[e];
        #pragma unroll
        for (int off = 16; off > 0; off >>= 1)
            den += __shfl_xor_sync(0xffffffffu, den, off);
        const float inv = 1.f / den;

        float ax = 0.f, ay = 0.f;
        int e = rp0;
        for (; e + 4 <= rp1; e += 4) {
            int s0 = g_csr_src[e],     s1 = g_csr_src[e + 1];
            int s2 = g_csr_src[e + 2], s3 = g_csr_src[e + 3];
            float w0 = g_exc[e],     w1 = g_exc[e + 1];
            float w2 = g_exc[e + 2], w3 = g_exc[e + 3];
            float2 v0 = h2f2(xlh[(size_t)s0 * 32 + lane]);
            float2 v1 = h2f2(xlh[(size_t)s1 * 32 + lane]);
            float2 v2 = h2f2(xlh[(size_t)s2 * 32 + lane]);
            float2 v3 = h2f2(xlh[(size_t)s3 * 32 + lane]);
            ax = fmaf(w0, v0.x, fmaf(w1, v1.x, fmaf(w2, v2.x, fmaf(w3, v3.x, ax))));
            ay = fmaf(w0, v0.y, fmaf(w1, v1.y, fmaf(w2, v2.y, fmaf(w3, v3.y, ay))));
        }
        for (; e < rp1; ++e) {
            int s = g_csr_src[e];
            float wgt = g_exc[e];
            float2 xv = h2f2(xlh[(size_t)s * 32 + lane]);
            ax = fmaf(wgt, xv.x, ax);
            ay = fmaf(wgt, xv.y, ay);
        }
        float2* out2 = reinterpret_cast<float2*>(g_out);
        out2[(size_t)d * 32 + lane] = make_float2(ax * inv, ay * inv);
    }
}

// ---------------- final MLP at node_idx + restore zero-invariants ------------
__global__ void fin_kernel(const int* __restrict__ idx, const float* __restrict__ bias2,
                           const float* __restrict__ y,
                           const float* __restrict__ W0, const float* __restrict__ b0,
                           const float* __restrict__ W1, const float* __restrict__ b1,
                           const float* __restrict__ W2, const float* __restrict__ b2,
                           float* __restrict__ dout, int M, int rf, int N) {
    // restore zero-invariants for the next launch (graph replay safe)
    int tid = blockIdx.x * blockDim.x + threadIdx.x;
    for (int z = tid; z < N; z += gridDim.x * blockDim.x) {
        g_degc[z] = 0; g_mark1[z] = 0; g_mark2[z] = 0;
    }
    if (tid == 0) { g_n1 = 0; g_n2 = 0; g_nasl1 = 0; g_nasl2 = 0; g_np = 0; }

    __shared__ float sh[4][64];
    __shared__ float sz[4][32];
    const int w = threadIdx.x >> 5, lane = threadIdx.x & 31;
    const int m = blockIdx.x * 4 + w;
    if (m >= M) return;
    const int v = idx[m];

    float h0 = fmaxf(g_out[(size_t)v * HID + lane]      + bias2[lane],      0.f);
    float h1 = fmaxf(g_out[(size_t)v * HID + 32 + lane] + bias2[32 + lane], 0.f);
    sh[w][lane] = h0; sh[w][32 + lane] = h1;
    __syncwarp();

    int k = v / rf;
    float y0 = y[2 * k], y1 = y[2 * k + 1];
    float q0 = fmaxf(y0 * W0[0] + y1 * W0[2] + b0[0], 0.f);
    float q1 = fmaxf(y0 * W0[1] + y1 * W0[3] + b0[1], 0.f);

    float z = b1[lane];
    #pragma unroll
    for (int j = 0; j < 64; ++j) z += sh[w][j] * W1[j * 32 + lane];
    z += q0 * W1[64 * 32 + lane] + q1 * W1[65 * 32 + lane];
    z = fmaxf(z, 0.f);
    sz[w][lane] = z;
    __syncwarp();

    float o = b2[lane];
    #pragma unroll
    for (int j = 0; j < 32; ++j) o += sz[w][j] * W2[j * 32 + lane];
    dout[m * 32 + lane] = o;
}

// ---------------- launch ------------------------------------------------------
extern "C" void kernel_launch(void* const* d_in, const int* in_sizes, int n_in,
                              void* d_out, int out_size) {
    const float* x    = (const float*)d_in[0];
    const float* ea   = (const float*)d_in[1];
    const float* y    = (const float*)d_in[2];
    const float* Wl1  = (const float*)d_in[3];
    const float* bl1  = (const float*)d_in[4];
    const float* Wr1  = (const float*)d_in[5];
    const float* br1  = (const float*)d_in[6];
    const float* We1  = (const float*)d_in[7];
    const float* att1 = (const float*)d_in[8];
    const float* bias1= (const float*)d_in[9];
    const float* Wl2  = (const float*)d_in[10];
    const float* bl2  = (const float*)d_in[11];
    const float* Wr2  = (const float*)d_in[12];
    const float* br2  = (const float*)d_in[13];
    const float* We2  = (const float*)d_in[14];
    const float* att2 = (const float*)d_in[15];
    const float* bias2= (const float*)d_in[16];
    const float* W0   = (const float*)d_in[17];
    const float* b0   = (const float*)d_in[18];
    const float* W1   = (const float*)d_in[19];
    const float* b1   = (const float*)d_in[20];
    const float* W2   = (const float*)d_in[21];
    const float* b2   = (const float*)d_in[22];
    const int*   ei   = (const int*)  d_in[23];
    const int*   nidx = (const int*)  d_in[24];

    const int N    = in_sizes[0] / FN;
    const int E    = in_sizes[23] / 2;
    const int M    = in_sizes[24];
    const int NG   = in_sizes[2] / 2;
    const int rf   = N / NG;

    const int EBLK = (E + 255) / 256;
    const int NB1K = (N + 1023) / 1024;
    const int LINB = (N + 127) / 128;

    // ---- active sets ----
    mark2_kernel   <<<(M + 255) / 256, 256>>>(nidx, M);
    markS_kernel   <<<EBLK, 256>>>(ei, E);

    // ---- compact CSR over T1 (one E-scan + small passes) ----
    collect_kernel <<<EBLK, 256>>>(ei, E);
    scanA_kernel   <<<NB1K, 1024>>>();
    scanB_kernel   <<<1, 128>>>(NB1K);
    scanC_kernel   <<<NB1K, 1024>>>();
    place_kernel   <<<1024, 256>>>(ea);
    prep_kernel    <<<512, 256>>>();

    // ---- layer 1: xl over all N, xr over T1 ----
    lin_f16_kernel<FN, 0, false><<<LINB, 256>>>(x, Wl1, bl1, nullptr, N, 0);
    lin_f16_kernel<FN, 1, false><<<LINB, 256>>>(x, Wr1, br1, nullptr, N, 1);
    edgeA_kernel<<<2048, 256>>>(We1, att1, 1);
    edgeB_kernel<<<1024, 256>>>(1);

    // ---- layer 2: xl over T1, xr over T2 ----
    lin_f16_kernel<HID, 1, true><<<LINB, 256>>>(x, Wl2, bl2, bias1, N, 0);
    lin_f16_kernel<HID, 2, true><<<LINB, 256>>>(x, Wr2, br2, bias1, N, 1);
    edgeA_kernel<<<512, 256>>>(We2, att2, 2);
    edgeB_kernel<<<256, 256>>>(2);

    // ---- final MLP at node_idx (also restores zero-invariants) ----
    fin_kernel<<<512, 128>>>(nidx, bias2, y, W0, b0, W1, b1, W2, b2,
                             (float*)d_out, M, rf, N);
}

// round 13
// speedup vs baseline: 3.6631x; 1.0416x over previous
#include <cuda_runtime.h>
#include <cuda_fp16.h>
#include <cstddef>

typedef unsigned long long ull;
typedef unsigned int uint;

// ---------------- problem constants (shapes fixed by the dataset) -----------
#define MAXN 100000
#define MAXE 1600000
#define MAXET (MAXE + MAXN)
#define MAXETP (MAXET + 16)   // padded: slot MAXET is a never-written zero row
#define FN   128     // node feature dim (layer1 input)
#define FE   32      // edge feature dim
#define HID  64

// ---------------- device scratch (static: no allocation allowed) ------------
__device__ __align__(16) __half g_xlh[MAXN * HID];  // source-side transform (fp16)
__device__ __align__(16) __half g_xrh[MAXN * HID];  // target-side transform (fp16)
__device__ float  g_out [MAXN * HID];       // layer output (valid at T1 nodes)
__device__ int    g_degc[MAXN];             // degree per T1 index (zero at entry)
__device__ int    g_mark1[MAXN];            // T1 index+1, 0 = inactive (zeroed by fin)
__device__ int    g_mark2[MAXN];            // T2 index+1, 0 = inactive (zeroed by fin)
__device__ int    g_rowptr[MAXN + 1];       // compact rowptr over T1 indices
__device__ int    g_cur [MAXN];
__device__ int    g_bsum[128];
__device__ int    g_csr_src[MAXETP];        // src node per compact slot
__device__ int    g_list1[MAXN];            // compacted T1 node list
__device__ int    g_list2[MAXN];            // compacted T2 node list
__device__ int2   g_pair_es[MAXET];         // (eid, src) of accepted edges
__device__ int2   g_pair_md[MAXET];         // (T1 idx, dst) of accepted edges
__device__ int    g_n1, g_n2, g_np;         // zero at entry (fin restores)
__device__ __align__(16) __half g_eap[(size_t)MAXETP * FE];  // permuted fp16 edge attrs

// ---------------- small helpers ---------------------------------------------
__device__ __forceinline__ void mma_f16(float acc[4], uint a0, uint a1, uint a2, uint a3,
                                        uint b0, uint b1) {
    asm volatile(
        "mma.sync.aligned.m16n8k16.row.col.f32.f16.f16.f32 "
        "{%0,%1,%2,%3}, {%4,%5,%6,%7}, {%8,%9}, {%0,%1,%2,%3};"
        : "+f"(acc[0]), "+f"(acc[1]), "+f"(acc[2]), "+f"(acc[3])
        : "r"(a0), "r"(a1), "r"(a2), "r"(a3), "r"(b0), "r"(b1));
}
__device__ __forceinline__ float2 h2f2(uint v) {
    __half2 h = *reinterpret_cast<__half2*>(&v);
    return __half22float2(h);
}
__device__ __forceinline__ uint f2h2(float x, float y) {
    __half2 h = __floats2half2_rn(x, y);
    return *reinterpret_cast<uint*>(&h);
}

// ================= active-set construction ===================================
__global__ void mark2_kernel(const int* __restrict__ nidx, int M) {
    int m = blockIdx.x * blockDim.x + threadIdx.x;
    if (m >= M) return;
    int d = nidx[m];
    if (atomicCAS(&g_mark2[d], 0, -1) == 0) {
        int p = atomicAdd(&g_n2, 1); g_list2[p] = d; g_mark2[d] = p + 1;
    }
    if (atomicCAS(&g_mark1[d], 0, -1) == 0) {
        int p = atomicAdd(&g_n1, 1); g_list1[p] = d; g_mark1[d] = p + 1;
    }
}

// T1 += sources of edges whose dst is in T2
__global__ void markS_kernel(const int* __restrict__ ei, int E) {
    int i = blockIdx.x * blockDim.x + threadIdx.x;
    if (i >= E) return;
    int d = ei[E + i];
    if (g_mark2[d]) {
        int s = ei[i];
        if (atomicCAS(&g_mark1[s], 0, -1) == 0) {
            int p = atomicAdd(&g_n1, 1); g_list1[p] = s; g_mark1[s] = p + 1;
        }
    }
}

// ================= compact CSR build (T1 segments only) =======================
// Single E-scan: filter + append pairs + degree count.
__global__ void collect_kernel(const int* __restrict__ ei, int E) {
    int i = blockIdx.x * blockDim.x + threadIdx.x;
    if (i >= E) return;
    int d = ei[E + i];
    int m = g_mark1[d];
    if (m <= 0) return;
    int j = atomicAdd(&g_np, 1);
    g_pair_es[j] = make_int2(i, ei[i]);
    g_pair_md[j] = make_int2(m - 1, d);
    atomicAdd(&g_degc[m - 1], 1);
}

// grid scan stage A over T1-index space: exclusive scan of (deg+1)
__global__ __launch_bounds__(1024) void scanA_kernel() {
    __shared__ int wsum[32];
    const int n1 = g_n1;
    const int i = blockIdx.x * 1024 + threadIdx.x;
    const int lane = threadIdx.x & 31, wid = threadIdx.x >> 5;
    int v = (i < n1) ? (g_degc[i] + 1) : 0;
    int s = v;
    #pragma unroll
    for (int off = 1; off < 32; off <<= 1) {
        int t = __shfl_up_sync(0xffffffffu, s, off);
        if (lane >= off) s += t;
    }
    if (lane == 31) wsum[wid] = s;
    __syncthreads();
    if (wid == 0) {
        int ws = wsum[lane];
        #pragma unroll
        for (int off = 1; off < 32; off <<= 1) {
            int t = __shfl_up_sync(0xffffffffu, ws, off);
            if (lane >= off) ws += t;
        }
        wsum[lane] = ws;
    }
    __syncthreads();
    int excl = s - v + (wid ? wsum[wid - 1] : 0);
    if (i < n1) g_rowptr[i] = excl;
    if (threadIdx.x == 1023) g_bsum[blockIdx.x] = excl + v;
}

__global__ void scanB_kernel(int nb) {
    __shared__ int sh[128];
    const int t = threadIdx.x;
    int v = (t < nb) ? g_bsum[t] : 0;
    sh[t] = v;
    __syncthreads();
    for (int off = 1; off < 128; off <<= 1) {
        int x = (t >= off) ? sh[t - off] : 0;
        __syncthreads();
        sh[t] += x;
        __syncthreads();
    }
    g_bsum[t] = sh[t] - v;
    if (t == 127) g_rowptr[g_n1] = sh[127];
}

__global__ __launch_bounds__(1024) void scanC_kernel() {
    const int n1 = g_n1;
    int i = blockIdx.x * 1024 + threadIdx.x;
    if (i < n1) {
        int rp = g_rowptr[i] + g_bsum[blockIdx.x];
        g_rowptr[i] = rp;
        g_cur[i]    = rp;
    }
}

// place accepted edges into compact slots + permute/convert edge attrs
__global__ void place_kernel(const float* __restrict__ ea) {
    const int np = g_np;
    const int stride = gridDim.x * blockDim.x;
    for (int j = blockIdx.x * blockDim.x + threadIdx.x; j < np; j += stride) {
        int2 es = g_pair_es[j];
        int2 md = g_pair_md[j];
        int pos = atomicAdd(&g_cur[md.x], 1);
        g_csr_src[pos] = es.y;
        const float4* r4 = reinterpret_cast<const float4*>(ea) + (size_t)es.x * 8;
        __half2* dst = reinterpret_cast<__half2*>(g_eap + (size_t)pos * FE);
        #pragma unroll
        for (int q = 0; q < 8; ++q) {
            float4 v = r4[q];
            dst[2 * q]     = __floats2half2_rn(v.x, v.y);
            dst[2 * q + 1] = __floats2half2_rn(v.z, v.w);
        }
    }
}

// self-loop mean per T1 segment (fills last slot of each segment)
__global__ void prep_kernel() {
    const int lane = threadIdx.x & 31;
    const int gws = gridDim.x * 8;
    const int n1 = g_n1;
    for (int widx = blockIdx.x * 8 + (threadIdx.x >> 5); widx < n1; widx += gws) {
        const int d = g_list1[widx];
        const int rp0 = g_rowptr[widx], rp1 = g_rowptr[widx + 1];
        const int last = rp1 - 1;            // self-loop slot
        float s = 0.f;
        int e = rp0;
        for (; e + 4 <= last; e += 4) {
            float a0 = __half2float(g_eap[(size_t)(e + 0) * FE + lane]);
            float a1 = __half2float(g_eap[(size_t)(e + 1) * FE + lane]);
            float a2 = __half2float(g_eap[(size_t)(e + 2) * FE + lane]);
            float a3 = __half2float(g_eap[(size_t)(e + 3) * FE + lane]);
            s += (a0 + a1) + (a2 + a3);
        }
        for (; e < last; ++e) s += __half2float(g_eap[(size_t)e * FE + lane]);
        float mean = s / (float)max(last - rp0, 1);
        g_eap[(size_t)last * FE + lane] = __float2half_rn(mean);
        if (lane == 0) g_csr_src[last] = d;
    }
}

// ---------------- single-output node linear via fp16 tensor MMA --------------
// SET: 0 = full N, 1 = g_list1, 2 = g_list2. HPREV: read g_out+bias1+relu.
// right: 0 -> g_xlh, 1 -> g_xrh. Block = 128 nodes, 8 warps x 16 rows.
template<int IN, int SET, bool HPREV>
__global__ __launch_bounds__(256) void lin_f16_kernel(
        const float* __restrict__ inp, const float* __restrict__ W,
        const float* __restrict__ bias, const float* __restrict__ prevBias,
        int N, int right) {
    const int nlim = (SET == 0) ? N : (SET == 1 ? g_n1 : g_n2);
    const int nb = blockIdx.x * 128;
    if (nb >= nlim) return;

    constexpr int KC = 16;                    // k per iteration (one k16 MMA step)
    __shared__ uint Xs[128][9];               // 8 k-pair words + pad
    __shared__ uint Ws[8][68];                // k-pair word x 64 cols + pad

    const int t = threadIdx.x;
    const int lane = t & 31;
    const int mt = t >> 5;                    // warp = m-tile 0..7
    const int g = lane >> 2, c = lane & 3;

    float acc[8][4];
    #pragma unroll
    for (int nt = 0; nt < 8; ++nt) {
        acc[nt][0] = acc[nt][1] = acc[nt][2] = acc[nt][3] = 0.f;
    }

    for (int kc = 0; kc < IN; kc += KC) {
        __syncthreads();
        for (int idx = t; idx < 128 * 8; idx += 256) {
            int row = idx >> 3, kw = idx & 7;
            int m = nb + row;
            float v0 = 0.f, v1 = 0.f;
            if (m < nlim) {
                int node = (SET == 0) ? m : (SET == 1 ? g_list1[m] : g_list2[m]);
                int j = kc + 2 * kw;
                if (HPREV) {
                    float2 hv = *reinterpret_cast<const float2*>(g_out + (size_t)node * HID + j);
                    v0 = fmaxf(hv.x + prevBias[j], 0.f);
                    v1 = fmaxf(hv.y + prevBias[j + 1], 0.f);
                } else {
                    float2 xv = *reinterpret_cast<const float2*>(inp + (size_t)node * IN + j);
                    v0 = xv.x; v1 = xv.y;
                }
            }
            Xs[row][kw] = f2h2(v0, v1);
        }
        for (int idx = t; idx < 8 * 64; idx += 256) {
            int kw = idx >> 6, col = idx & 63;
            int k = kc + 2 * kw;
            Ws[kw][col] = f2h2(W[k * HID + col], W[(k + 1) * HID + col]);
        }
        __syncthreads();
        uint a0 = Xs[mt * 16 + g    ][c];
        uint a1 = Xs[mt * 16 + g + 8][c];
        uint a2 = Xs[mt * 16 + g    ][c + 4];
        uint a3 = Xs[mt * 16 + g + 8][c + 4];
        #pragma unroll
        for (int nt = 0; nt < 8; ++nt) {
            int col = nt * 8 + g;
            mma_f16(acc[nt], a0, a1, a2, a3, Ws[c][col], Ws[c + 4][col]);
        }
    }

    uint* dsth = reinterpret_cast<uint*>(right ? g_xrh : g_xlh);
    const int m0 = nb + mt * 16 + g;
    const int m1 = m0 + 8;
    const int node0 = (m0 < nlim) ? ((SET == 0) ? m0 : (SET == 1 ? g_list1[m0] : g_list2[m0])) : -1;
    const int node1 = (m1 < nlim) ? ((SET == 0) ? m1 : (SET == 1 ? g_list1[m1] : g_list2[m1])) : -1;
    #pragma unroll
    for (int nt = 0; nt < 8; ++nt) {
        int colL = nt * 8 + 2 * c;
        float bx = bias[colL], by = bias[colL + 1];
        if (node0 >= 0)
            dsth[(size_t)node0 * 32 + nt * 4 + c] = f2h2(acc[nt][0] + bx, acc[nt][1] + by);
        if (node1 >= 0)
            dsth[(size_t)node1 * 32 + nt * 4 + c] = f2h2(acc[nt][2] + bx, acc[nt][3] + by);
    }
}

// ---------------- fused edge pass: warp-per-segment GATv2 --------------------
// For each destination segment: e-GEMM logits (fp16 MMA), exp, denominator,
// and Sigma(exp * xl[src]) accumulated in registers; one write of out[d].
__global__ __launch_bounds__(256) void edge_fused_kernel(
        const float* __restrict__ We, const float* __restrict__ att, int layer) {
    const int n = (layer == 1) ? g_n1 : g_n2;
    const int t = threadIdx.x;
    const int lane = t & 31;
    const int g = lane >> 2;                 // row group 0..7
    const int c = lane & 3;                  // col-in-group 0..3
    const int gws = gridDim.x * 8;

    // preload B fragments (We as fp16) and att pairs into registers
    uint breg[8][2][2];
    float2 areg[8];
    #pragma unroll
    for (int nt = 0; nt < 8; ++nt) {
        const int nn = nt * 8 + g;
        #pragma unroll
        for (int ks = 0; ks < 2; ++ks) {
            int k0 = ks * 16 + 2 * c;
            breg[nt][ks][0] = f2h2(We[k0 * HID + nn],       We[(k0 + 1) * HID + nn]);
            breg[nt][ks][1] = f2h2(We[(k0 + 8) * HID + nn], We[(k0 + 9) * HID + nn]);
        }
        areg[nt] = reinterpret_cast<const float2*>(att)[nt * 4 + c];
    }

    const uint* xlh = reinterpret_cast<const uint*>(g_xlh);
    const uint* xrh = reinterpret_cast<const uint*>(g_xrh);

    for (int widx = blockIdx.x * 8 + (t >> 5); widx < n; widx += gws) {
        int d, m;
        if (layer == 1) { d = g_list1[widx]; m = widx; }
        else            { d = g_list2[widx]; m = g_mark1[d] - 1; }
        const int rp0 = g_rowptr[m], rp1 = g_rowptr[m + 1];

        // xr[d] loaded once per segment
        float2 xr[8];
        #pragma unroll
        for (int nt = 0; nt < 8; ++nt)
            xr[nt] = h2f2(xrh[(size_t)d * 32 + nt * 4 + c]);

        float den = 0.f;
        float2 o[8];
        #pragma unroll
        for (int nt = 0; nt < 8; ++nt) o[nt] = make_float2(0.f, 0.f);

        for (int base = rp0; base < rp1; base += 16) {
            const int rowA = base + g;
            const int rowB = rowA + 8;
            const bool vA = rowA < rp1, vB = rowB < rp1;
            const int slotA = vA ? rowA : MAXET;   // pad slot: zeros
            const int slotB = vB ? rowB : MAXET;
            const int sA = g_csr_src[slotA], sB = g_csr_src[slotB];
            const uint* pA = reinterpret_cast<const uint*>(g_eap + (size_t)slotA * FE);
            const uint* pB = reinterpret_cast<const uint*>(g_eap + (size_t)slotB * FE);

            uint afr[2][4];
            #pragma unroll
            for (int ks = 0; ks < 2; ++ks) {
                afr[ks][0] = pA[ks * 8 + c];
                afr[ks][1] = pB[ks * 8 + c];
                afr[ks][2] = pA[ks * 8 + c + 4];
                afr[ks][3] = pB[ks * 8 + c + 4];
            }

            float2 xlA[8], xlB[8];
            float partA = 0.f, partB = 0.f;
            #pragma unroll
            for (int nt = 0; nt < 8; ++nt) {
                float acc[4] = {0.f, 0.f, 0.f, 0.f};
                mma_f16(acc, afr[0][0], afr[0][1], afr[0][2], afr[0][3],
                        breg[nt][0][0], breg[nt][0][1]);
                mma_f16(acc, afr[1][0], afr[1][1], afr[1][2], afr[1][3],
                        breg[nt][1][0], breg[nt][1][1]);
                xlA[nt] = h2f2(xlh[(size_t)sA * 32 + nt * 4 + c]);
                xlB[nt] = h2f2(xlh[(size_t)sB * 32 + nt * 4 + c]);
                float u0 = acc[0] + xlA[nt].x + xr[nt].x;
                float u1 = acc[1] + xlA[nt].y + xr[nt].y;
                float u2 = acc[2] + xlB[nt].x + xr[nt].x;
                float u3 = acc[3] + xlB[nt].y + xr[nt].y;
                u0 = fmaxf(u0, 0.f) + 0.2f * fminf(u0, 0.f);
                u1 = fmaxf(u1, 0.f) + 0.2f * fminf(u1, 0.f);
                u2 = fmaxf(u2, 0.f) + 0.2f * fminf(u2, 0.f);
                u3 = fmaxf(u3, 0.f) + 0.2f * fminf(u3, 0.f);
                partA = fmaf(u0, areg[nt].x, fmaf(u1, areg[nt].y, partA));
                partB = fmaf(u2, areg[nt].x, fmaf(u3, areg[nt].y, partB));
            }
            partA += __shfl_xor_sync(0xffffffffu, partA, 1);
            partA += __shfl_xor_sync(0xffffffffu, partA, 2);
            partB += __shfl_xor_sync(0xffffffffu, partB, 1);
            partB += __shfl_xor_sync(0xffffffffu, partB, 2);
            const float eA = vA ? __expf(partA) : 0.f;
            const float eB = vB ? __expf(partB) : 0.f;
            den += eA + eB;
            #pragma unroll
            for (int nt = 0; nt < 8; ++nt) {
                o[nt].x = fmaf(eA, xlA[nt].x, fmaf(eB, xlB[nt].x, o[nt].x));
                o[nt].y = fmaf(eA, xlA[nt].y, fmaf(eB, xlB[nt].y, o[nt].y));
            }
        }

        // reduce across the 8 row-groups (lane = g*4 + c)
        #pragma unroll
        for (int off = 4; off <= 16; off <<= 1) {
            den += __shfl_xor_sync(0xffffffffu, den, off);
            #pragma unroll
            for (int nt = 0; nt < 8; ++nt) {
                o[nt].x += __shfl_xor_sync(0xffffffffu, o[nt].x, off);
                o[nt].y += __shfl_xor_sync(0xffffffffu, o[nt].y, off);
            }
        }
        const float inv = 1.f / den;
        if (g == 0) {
            float2* out2 = reinterpret_cast<float2*>(g_out);
            #pragma unroll
            for (int nt = 0; nt < 8; ++nt)
                out2[(size_t)d * 32 + nt * 4 + c] = make_float2(o[nt].x * inv, o[nt].y * inv);
        }
    }
}

// ---------------- final MLP at node_idx + restore zero-invariants ------------
__global__ void fin_kernel(const int* __restrict__ idx, const float* __restrict__ bias2,
                           const float* __restrict__ y,
                           const float* __restrict__ W0, const float* __restrict__ b0,
                           const float* __restrict__ W1, const float* __restrict__ b1,
                           const float* __restrict__ W2, const float* __restrict__ b2,
                           float* __restrict__ dout, int M, int rf, int N) {
    // restore zero-invariants for the next launch (graph replay safe)
    int tid = blockIdx.x * blockDim.x + threadIdx.x;
    for (int z = tid; z < N; z += gridDim.x * blockDim.x) {
        g_degc[z] = 0; g_mark1[z] = 0; g_mark2[z] = 0;
    }
    if (tid == 0) { g_n1 = 0; g_n2 = 0; g_np = 0; }

    __shared__ float sh[4][64];
    __shared__ float sz[4][32];
    const int w = threadIdx.x >> 5, lane = threadIdx.x & 31;
    const int m = blockIdx.x * 4 + w;
    if (m >= M) return;
    const int v = idx[m];

    float h0 = fmaxf(g_out[(size_t)v * HID + lane]      + bias2[lane],      0.f);
    float h1 = fmaxf(g_out[(size_t)v * HID + 32 + lane] + bias2[32 + lane], 0.f);
    sh[w][lane] = h0; sh[w][32 + lane] = h1;
    __syncwarp();

    int k = v / rf;
    float y0 = y[2 * k], y1 = y[2 * k + 1];
    float q0 = fmaxf(y0 * W0[0] + y1 * W0[2] + b0[0], 0.f);
    float q1 = fmaxf(y0 * W0[1] + y1 * W0[3] + b0[1], 0.f);

    float z = b1[lane];
    #pragma unroll
    for (int j = 0; j < 64; ++j) z += sh[w][j] * W1[j * 32 + lane];
    z += q0 * W1[64 * 32 + lane] + q1 * W1[65 * 32 + lane];
    z = fmaxf(z, 0.f);
    sz[w][lane] = z;
    __syncwarp();

    float o = b2[lane];
    #pragma unroll
    for (int j = 0; j < 32; ++j) o += sz[w][j] * W2[j * 32 + lane];
    dout[m * 32 + lane] = o;
}

// ---------------- launch ------------------------------------------------------
extern "C" void kernel_launch(void* const* d_in, const int* in_sizes, int n_in,
                              void* d_out, int out_size) {
    const float* x    = (const float*)d_in[0];
    const float* ea   = (const float*)d_in[1];
    const float* y    = (const float*)d_in[2];
    const float* Wl1  = (const float*)d_in[3];
    const float* bl1  = (const float*)d_in[4];
    const float* Wr1  = (const float*)d_in[5];
    const float* br1  = (const float*)d_in[6];
    const float* We1  = (const float*)d_in[7];
    const float* att1 = (const float*)d_in[8];
    const float* bias1= (const float*)d_in[9];
    const float* Wl2  = (const float*)d_in[10];
    const float* bl2  = (const float*)d_in[11];
    const float* Wr2  = (const float*)d_in[12];
    const float* br2  = (const float*)d_in[13];
    const float* We2  = (const float*)d_in[14];
    const float* att2 = (const float*)d_in[15];
    const float* bias2= (const float*)d_in[16];
    const float* W0   = (const float*)d_in[17];
    const float* b0   = (const float*)d_in[18];
    const float* W1   = (const float*)d_in[19];
    const float* b1   = (const float*)d_in[20];
    const float* W2   = (const float*)d_in[21];
    const float* b2   = (const float*)d_in[22];
    const int*   ei   = (const int*)  d_in[23];
    const int*   nidx = (const int*)  d_in[24];

    const int N    = in_sizes[0] / FN;
    const int E    = in_sizes[23] / 2;
    const int M    = in_sizes[24];
    const int NG   = in_sizes[2] / 2;
    const int rf   = N / NG;

    const int EBLK = (E + 255) / 256;
    const int NB1K = (N + 1023) / 1024;
    const int LINB = (N + 127) / 128;

    // ---- active sets ----
    mark2_kernel   <<<(M + 255) / 256, 256>>>(nidx, M);
    markS_kernel   <<<EBLK, 256>>>(ei, E);

    // ---- compact CSR over T1 (one E-scan + small passes) ----
    collect_kernel <<<EBLK, 256>>>(ei, E);
    scanA_kernel   <<<NB1K, 1024>>>();
    scanB_kernel   <<<1, 128>>>(NB1K);
    scanC_kernel   <<<NB1K, 1024>>>();
    place_kernel   <<<1024, 256>>>(ea);
    prep_kernel    <<<512, 256>>>();

    // ---- layer 1: xl over all N, xr over T1; fused edge pass over T1 ----
    lin_f16_kernel<FN, 0, false><<<LINB, 256>>>(x, Wl1, bl1, nullptr, N, 0);
    lin_f16_kernel<FN, 1, false><<<LINB, 256>>>(x, Wr1, br1, nullptr, N, 1);
    edge_fused_kernel<<<1024, 256>>>(We1, att1, 1);

    // ---- layer 2: xl over T1, xr over T2; fused edge pass over T2 ----
    lin_f16_kernel<HID, 1, true><<<LINB, 256>>>(x, Wl2, bl2, bias1, N, 0);
    lin_f16_kernel<HID, 2, true><<<LINB, 256>>>(x, Wr2, br2, bias1, N, 1);
    edge_fused_kernel<<<128, 256>>>(We2, att2, 2);

    // ---- final MLP at node_idx (also restores zero-invariants) ----
    fin_kernel<<<512, 128>>>(nidx, bias2, y, W0, b0, W1, b1, W2, b2,
                             (float*)d_out, M, rf, N);
}